// round 14
// baseline (speedup 1.0000x reference)
#include <cuda_runtime.h>
#include <cuda_bf16.h>
#include <math.h>
#include <stdint.h>

// Problem constants
#define L_   6
#define B_   2
#define T_   1024
#define D_   1024
#define H_   16
#define DH_  64
#define FF_  4096
#define V_   32000
#define KNB_ 4
#define DT_  0.1f

// ---------------------------------------------------------------------------
// Scratch
// ---------------------------------------------------------------------------
__device__ float g_x[B_ * T_ * D_];
__device__ float g_scores[(size_t)B_ * H_ * T_ * T_];

#define W_QKV_OFF  ((size_t)0)
#define W_QKV_N    ((size_t)L_ * 3 * D_ * D_)
#define W_OUT_OFF  (W_QKV_OFF + W_QKV_N)
#define W_OUT_N    ((size_t)L_ * D_ * D_)
#define W_FC1_OFF  (W_OUT_OFF + W_OUT_N)
#define W_FC1_N    ((size_t)L_ * FF_ * D_)
#define W_FC2_OFF  (W_FC1_OFF + W_FC1_N)
#define W_FC2_N    ((size_t)L_ * D_ * FF_)
#define W_HEAD_OFF (W_FC2_OFF + W_FC2_N)
#define W_HEAD_N   ((size_t)V_ * D_)
#define W_TOTAL    (W_HEAD_OFF + W_HEAD_N)

__device__ __nv_bfloat16 g_w_hi[W_TOTAL];
__device__ __nv_bfloat16 g_w_lo[W_TOTAL];
__device__ __nv_bfloat16 g_act_hi[B_ * T_ * D_];
__device__ __nv_bfloat16 g_act_lo[B_ * T_ * D_];
__device__ __nv_bfloat16 g_ff_hi[B_ * T_ * FF_];
__device__ __nv_bfloat16 g_ff_lo[B_ * T_ * FF_];
__device__ __nv_bfloat16 g_qkv_hi[B_ * T_ * 3 * D_];
__device__ __nv_bfloat16 g_qkv_lo[B_ * T_ * 3 * D_];
__device__ __nv_bfloat16 g_p_hi[(size_t)B_ * H_ * T_ * T_];
__device__ __nv_bfloat16 g_p_lo[(size_t)B_ * H_ * T_ * T_];
__device__ __nv_bfloat16 g_vt_hi[B_ * H_ * DH_ * T_];
__device__ __nv_bfloat16 g_vt_lo[B_ * H_ * DH_ * T_];

// ---------------------------------------------------------------------------
// helpers
// ---------------------------------------------------------------------------
__device__ __forceinline__ uint32_t smem_u32(const void* p) {
    uint32_t a;
    asm("{ .reg .u64 t; cvta.to.shared.u64 t, %1; cvt.u32.u64 %0, t; }" : "=r"(a) : "l"(p));
    return a;
}
__device__ __forceinline__ void ldmatrix_x4(uint32_t* r, uint32_t addr) {
    asm volatile("ldmatrix.sync.aligned.m8n8.x4.shared.b16 {%0,%1,%2,%3},[%4];"
                 : "=r"(r[0]), "=r"(r[1]), "=r"(r[2]), "=r"(r[3]) : "r"(addr));
}
__device__ __forceinline__ void mma_bf16(float* c, const uint32_t* a, const uint32_t* b) {
    asm volatile(
        "mma.sync.aligned.m16n8k16.row.col.f32.bf16.bf16.f32 "
        "{%0,%1,%2,%3},{%4,%5,%6,%7},{%8,%9},{%0,%1,%2,%3};"
        : "+f"(c[0]), "+f"(c[1]), "+f"(c[2]), "+f"(c[3])
        : "r"(a[0]), "r"(a[1]), "r"(a[2]), "r"(a[3]), "r"(b[0]), "r"(b[1]));
}
#define CP_ASYNC(dst, src) \
    asm volatile("cp.async.cg.shared.global [%0],[%1],16;" :: "r"(dst), "l"(src))
#define CP_COMMIT() asm volatile("cp.async.commit_group;")
#define CP_WAIT(N)  asm volatile("cp.async.wait_group %0;" :: "n"(N))

__device__ __forceinline__ void split2(float x, float y, uint32_t& h, uint32_t& l) {
    __nv_bfloat16 hx = __float2bfloat16(x);
    __nv_bfloat16 hy = __float2bfloat16(y);
    __nv_bfloat16 lx = __float2bfloat16(x - __bfloat162float(hx));
    __nv_bfloat16 ly = __float2bfloat16(y - __bfloat162float(hy));
    h = (uint32_t)__bfloat16_as_ushort(hx) | ((uint32_t)__bfloat16_as_ushort(hy) << 16);
    l = (uint32_t)__bfloat16_as_ushort(lx) | ((uint32_t)__bfloat16_as_ushort(ly) << 16);
}
__device__ __forceinline__ float gelu_f(float t) {
    float u = 0.7978845608028654f * (t + 0.044715f * t * t * t);
    return 0.5f * t * (1.0f + tanhf(u));
}

// ---------------------------------------------------------------------------
// fp32 -> bf16 hi/lo split (weights only)
// ---------------------------------------------------------------------------
__global__ void conv_hilo(const float* __restrict__ src,
                          __nv_bfloat16* __restrict__ hi,
                          __nv_bfloat16* __restrict__ lo, int n4) {
    int i = blockIdx.x * 256 + threadIdx.x;
    if (i >= n4) return;
    float4 v = ((const float4*)src)[i];
    uint2 ho, lu;
    split2(v.x, v.y, ho.x, lu.x);
    split2(v.z, v.w, ho.y, lu.y);
    *(uint2*)(hi + (size_t)4 * i) = ho;
    *(uint2*)(lo + (size_t)4 * i) = lu;
}

// ---------------------------------------------------------------------------
// HMMA NT-GEMM: BM x 128 CTA tile, BK=32, 2-stage cp.async.
//  <256,512,1>: 16 warps (4x4 warp grid) — lower smem-read/MAC, for big grids.
//  <128,256,2>: 8 warps (2x4), 2 CTAs/SM — for M-split N=1024 GEMMs.
// modes: 0 bias+store, 1 bias+add+store, 2 bias+gelu->hi/lo, 3 bias->hi/lo.
// ---------------------------------------------------------------------------
#define RS_   80
#define BT_   (128 * RS_)          // 10240, B tile bytes (BN=128 fixed)

template<int BM, int TH, int NB>
__global__ __launch_bounds__(TH, NB)
void hmma_gemm(const __nv_bfloat16* __restrict__ Ahi, const __nv_bfloat16* __restrict__ Alo,
               const __nv_bfloat16* __restrict__ Bhi, const __nv_bfloat16* __restrict__ Blo,
               const float* __restrict__ bias, float* __restrict__ C,
               __nv_bfloat16* __restrict__ Ohi, __nv_bfloat16* __restrict__ Olo,
               int N, int Kd, int mode) {
    constexpr int ATB = BM * RS_;              // A tile bytes
    constexpr int STG = 2 * ATB + 2 * BT_;     // stage bytes
    constexpr int WR  = BM / 64;               // warp rows
    constexpr int AI  = (BM * 4) / TH;         // A loader iterations
    constexpr int BI  = 512 / TH;              // B loader iterations
    extern __shared__ char sm[];
    uint32_t smb = smem_u32(sm);
    int tid = threadIdx.x, wid = tid >> 5, lane = tid & 31;
    size_t m0 = (size_t)blockIdx.y * BM;
    size_t n0 = (size_t)blockIdx.x * 128;
    int wm = (wid % WR) * 64;
    int wn = (wid / WR) * 32;

    const __nv_bfloat16* Ah = Ahi + m0 * (size_t)Kd;
    const __nv_bfloat16* Al = Alo + m0 * (size_t)Kd;
    const __nv_bfloat16* Bh = Bhi + n0 * (size_t)Kd;
    const __nv_bfloat16* Bl = Blo + n0 * (size_t)Kd;

    auto load_stage = [&](int i, int s) {
        int k0 = i << 5;
        uint32_t sb = smb + s * STG;
        #pragma unroll
        for (int t = 0; t < AI; t++) {
            int idx = tid + t * TH;
            int row = idx >> 2, ch = idx & 3;
            size_t go = (size_t)row * Kd + k0 + ch * 8;
            uint32_t so = row * RS_ + ch * 16;
            CP_ASYNC(sb + so,        Ah + go);
            CP_ASYNC(sb + ATB + so,  Al + go);
        }
        #pragma unroll
        for (int t = 0; t < BI; t++) {
            int idx = tid + t * TH;
            int row = idx >> 2, ch = idx & 3;
            size_t go = (size_t)row * Kd + k0 + ch * 8;
            uint32_t so = row * RS_ + ch * 16;
            CP_ASYNC(sb + 2 * ATB + so,       Bh + go);
            CP_ASYNC(sb + 2 * ATB + BT_ + so, Bl + go);
        }
        CP_COMMIT();
    };

    float acc[4][4][4];
    #pragma unroll
    for (int a = 0; a < 4; a++)
        #pragma unroll
        for (int b = 0; b < 4; b++)
            #pragma unroll
            for (int c = 0; c < 4; c++) acc[a][b][c] = 0.f;

    int NC = Kd >> 5;
    load_stage(0, 0);

    int r16  = lane & 15;
    int ah16 = (lane >> 4) * 16;
    int brow = ((lane >> 4) & 1) * 8 + (lane & 7);
    int bo16 = ((lane >> 3) & 1) * 16;

    for (int i = 0; i < NC; i++) {
        int s = i & 1;
        if (i + 1 < NC) { load_stage(i + 1, s ^ 1); CP_WAIT(1); }
        else            { CP_WAIT(0); }
        __syncthreads();

        uint32_t sa = smb + s * STG;
        #pragma unroll
        for (int j = 0; j < 2; j++) {
            uint32_t a_hi[4][4], a_lo[4][4];
            #pragma unroll
            for (int mt = 0; mt < 4; mt++) {
                uint32_t addr = sa + (wm + mt * 16 + r16) * RS_ + ah16 + j * 32;
                ldmatrix_x4(a_hi[mt], addr);
                ldmatrix_x4(a_lo[mt], addr + ATB);
            }
            uint32_t b_hi[2][4], b_lo[2][4];
            #pragma unroll
            for (int p = 0; p < 2; p++) {
                uint32_t addr = sa + 2 * ATB + (wn + p * 16 + brow) * RS_ + bo16 + j * 32;
                ldmatrix_x4(b_hi[p], addr);
                ldmatrix_x4(b_lo[p], addr + BT_);
            }
            #pragma unroll
            for (int mt = 0; mt < 4; mt++)
                #pragma unroll
                for (int nt = 0; nt < 4; nt++)
                    mma_bf16(acc[mt][nt], a_hi[mt], &b_hi[nt >> 1][(nt & 1) * 2]);
            #pragma unroll
            for (int mt = 0; mt < 4; mt++)
                #pragma unroll
                for (int nt = 0; nt < 4; nt++)
                    mma_bf16(acc[mt][nt], a_hi[mt], &b_lo[nt >> 1][(nt & 1) * 2]);
            #pragma unroll
            for (int mt = 0; mt < 4; mt++)
                #pragma unroll
                for (int nt = 0; nt < 4; nt++)
                    mma_bf16(acc[mt][nt], a_lo[mt], &b_hi[nt >> 1][(nt & 1) * 2]);
        }
        __syncthreads();
    }

    int gr = lane >> 2;
    int gc = (lane & 3) * 2;
    #pragma unroll
    for (int mt = 0; mt < 4; mt++) {
        size_t row = m0 + wm + mt * 16 + gr;
        #pragma unroll
        for (int nt = 0; nt < 4; nt++) {
            size_t col = n0 + wn + nt * 8 + gc;
            float2 bv = *(const float2*)(bias + col);
            float v00 = acc[mt][nt][0] + bv.x, v01 = acc[mt][nt][1] + bv.y;
            float v10 = acc[mt][nt][2] + bv.x, v11 = acc[mt][nt][3] + bv.y;
            size_t o0 = row * (size_t)N + col;
            size_t o1 = (row + 8) * (size_t)N + col;
            if (mode >= 2) {
                if (mode == 2) {
                    v00 = gelu_f(v00); v01 = gelu_f(v01);
                    v10 = gelu_f(v10); v11 = gelu_f(v11);
                }
                uint32_t h0, l0, h1, l1;
                split2(v00, v01, h0, l0);
                split2(v10, v11, h1, l1);
                *(uint32_t*)(Ohi + o0) = h0; *(uint32_t*)(Olo + o0) = l0;
                *(uint32_t*)(Ohi + o1) = h1; *(uint32_t*)(Olo + o1) = l1;
            } else {
                if (mode == 1) {
                    float2 a0 = *(float2*)(C + o0), a1 = *(float2*)(C + o1);
                    v00 += a0.x; v01 += a0.y; v10 += a1.x; v11 += a1.y;
                }
                float2 w0 = {v00, v01}, w1 = {v10, v11};
                *(float2*)(C + o0) = w0;
                *(float2*)(C + o1) = w1;
            }
        }
    }
}

#define GSM256_ (2 * (2 * 256 * RS_ + 2 * BT_))   // 122880
#define GSM128_ (2 * (2 * 128 * RS_ + 2 * BT_))   // 81920

// ---------------------------------------------------------------------------
// HMMA attention scores: per (b,h) 128x128 tile, K = DH = 64 in one stage.
// ---------------------------------------------------------------------------
#define SRS_  144
#define SAT_  (128 * SRS_)
#define SSM_  (4 * SAT_)

__global__ __launch_bounds__(256, 2)
void scores_hmma(const __nv_bfloat16* __restrict__ qh,
                 const __nv_bfloat16* __restrict__ ql, float scale) {
    extern __shared__ char sm[];
    uint32_t smb = smem_u32(sm);
    int tid = threadIdx.x, wid = tid >> 5, lane = tid & 31;
    int bh = blockIdx.z;
    int b = bh >> 4, h = bh & 15;
    size_t m0 = (size_t)blockIdx.y * 128;
    size_t n0 = (size_t)blockIdx.x * 128;
    int wm = (wid & 1) * 64;
    int wn = (wid >> 1) * 32;

    const __nv_bfloat16* Ah = qh + ((size_t)b * T_ + m0) * (3 * D_) + h * DH_;
    const __nv_bfloat16* Al = ql + ((size_t)b * T_ + m0) * (3 * D_) + h * DH_;
    const __nv_bfloat16* Bh = qh + ((size_t)b * T_ + n0) * (3 * D_) + D_ + h * DH_;
    const __nv_bfloat16* Bl = ql + ((size_t)b * T_ + n0) * (3 * D_) + D_ + h * DH_;

    const __nv_bfloat16* srcs[4] = {Ah, Al, Bh, Bl};
    #pragma unroll
    for (int tile = 0; tile < 4; tile++) {
        #pragma unroll
        for (int t = 0; t < 4; t++) {
            int idx = tid + t * 256;
            int r = idx >> 3, ch = idx & 7;
            CP_ASYNC(smb + tile * SAT_ + r * SRS_ + ch * 16,
                     srcs[tile] + (size_t)r * (3 * D_) + ch * 8);
        }
    }
    CP_COMMIT();
    CP_WAIT(0);
    __syncthreads();

    float acc[4][4][4];
    #pragma unroll
    for (int a = 0; a < 4; a++)
        #pragma unroll
        for (int bq = 0; bq < 4; bq++)
            #pragma unroll
            for (int c = 0; c < 4; c++) acc[a][bq][c] = 0.f;

    int r16  = lane & 15;
    int ah16 = (lane >> 4) * 16;
    int brow = ((lane >> 4) & 1) * 8 + (lane & 7);
    int bo16 = ((lane >> 3) & 1) * 16;

    #pragma unroll
    for (int j = 0; j < 4; j++) {
        uint32_t a_hi[4][4], a_lo[4][4];
        #pragma unroll
        for (int mt = 0; mt < 4; mt++) {
            uint32_t addr = smb + (wm + mt * 16 + r16) * SRS_ + ah16 + j * 32;
            ldmatrix_x4(a_hi[mt], addr);
            ldmatrix_x4(a_lo[mt], addr + SAT_);
        }
        uint32_t b_hi[2][4], b_lo[2][4];
        #pragma unroll
        for (int p = 0; p < 2; p++) {
            uint32_t addr = smb + 2 * SAT_ + (wn + p * 16 + brow) * SRS_ + bo16 + j * 32;
            ldmatrix_x4(b_hi[p], addr);
            ldmatrix_x4(b_lo[p], addr + SAT_);
        }
        #pragma unroll
        for (int mt = 0; mt < 4; mt++)
            #pragma unroll
            for (int nt = 0; nt < 4; nt++)
                mma_bf16(acc[mt][nt], a_hi[mt], &b_hi[nt >> 1][(nt & 1) * 2]);
        #pragma unroll
        for (int mt = 0; mt < 4; mt++)
            #pragma unroll
            for (int nt = 0; nt < 4; nt++)
                mma_bf16(acc[mt][nt], a_hi[mt], &b_lo[nt >> 1][(nt & 1) * 2]);
        #pragma unroll
        for (int mt = 0; mt < 4; mt++)
            #pragma unroll
            for (int nt = 0; nt < 4; nt++)
                mma_bf16(acc[mt][nt], a_lo[mt], &b_hi[nt >> 1][(nt & 1) * 2]);
    }

    float* srow = g_scores + (size_t)bh * T_ * T_;
    int gr = lane >> 2;
    int gc = (lane & 3) * 2;
    #pragma unroll
    for (int mt = 0; mt < 4; mt++) {
        size_t row = m0 + wm + mt * 16 + gr;
        #pragma unroll
        for (int nt = 0; nt < 4; nt++) {
            size_t col = n0 + wn + nt * 8 + gc;
            float2 w0 = {acc[mt][nt][0] * scale, acc[mt][nt][1] * scale};
            float2 w1 = {acc[mt][nt][2] * scale, acc[mt][nt][3] * scale};
            *(float2*)(srow + row * T_ + col) = w0;
            *(float2*)(srow + (row + 8) * T_ + col) = w1;
        }
    }
}

// ---------------------------------------------------------------------------
// V transpose: [b,k,h,dh] hi/lo -> [b,h,dh,k] hi/lo
// ---------------------------------------------------------------------------
__global__ void vt_kernel(const __nv_bfloat16* __restrict__ qh,
                          const __nv_bfloat16* __restrict__ ql,
                          __nv_bfloat16* __restrict__ vth,
                          __nv_bfloat16* __restrict__ vtl) {
    __shared__ __align__(16) __nv_bfloat16 th[64][72];
    __shared__ __align__(16) __nv_bfloat16 tl[64][72];
    int bh = blockIdx.y;
    int b = bh >> 4, h = bh & 15;
    int k0 = blockIdx.x * 64;
    int tid = threadIdx.x;
    const __nv_bfloat16* inh = qh + ((size_t)b * T_ + k0) * (3 * D_) + 2 * D_ + h * DH_;
    const __nv_bfloat16* inl = ql + ((size_t)b * T_ + k0) * (3 * D_) + 2 * D_ + h * DH_;
    #pragma unroll
    for (int t = 0; t < 2; t++) {
        int idx = tid + t * 256;
        int r = idx >> 3, c = idx & 7;
        *(uint4*)&th[r][c * 8] = *(const uint4*)(inh + (size_t)r * (3 * D_) + c * 8);
        *(uint4*)&tl[r][c * 8] = *(const uint4*)(inl + (size_t)r * (3 * D_) + c * 8);
    }
    __syncthreads();
    #pragma unroll
    for (int t = 0; t < 2; t++) {
        int idx = tid + t * 256;
        int dh = idx >> 3, c = idx & 7;
        __nv_bfloat16 bh8[8], bl8[8];
        #pragma unroll
        for (int u = 0; u < 8; u++) { bh8[u] = th[c * 8 + u][dh]; bl8[u] = tl[c * 8 + u][dh]; }
        size_t off = ((size_t)bh * DH_ + dh) * T_ + k0 + c * 8;
        *(uint4*)(vth + off) = *(uint4*)bh8;
        *(uint4*)(vtl + off) = *(uint4*)bl8;
    }
}

// ---------------------------------------------------------------------------
// Row softmax over T=1024: fp32 scores -> P bf16 hi/lo
// ---------------------------------------------------------------------------
__global__ void softmax_kernel(__nv_bfloat16* __restrict__ phi,
                               __nv_bfloat16* __restrict__ plo) {
    size_t row = blockIdx.x;
    int c = threadIdx.x;
    const float4* rp = (const float4*)(g_scores + row * T_);
    float4 v = rp[c];
    float m = fmaxf(fmaxf(v.x, v.y), fmaxf(v.z, v.w));
    #pragma unroll
    for (int o = 16; o; o >>= 1) m = fmaxf(m, __shfl_down_sync(0xFFFFFFFFu, m, o));
    __shared__ float sm[8];
    __shared__ float bm, bs;
    if ((c & 31) == 0) sm[c >> 5] = m;
    __syncthreads();
    if (c == 0) {
        float mm = sm[0];
        #pragma unroll
        for (int i = 1; i < 8; i++) mm = fmaxf(mm, sm[i]);
        bm = mm;
    }
    __syncthreads();
    float mm = bm;
    v.x = __expf(v.x - mm); v.y = __expf(v.y - mm);
    v.z = __expf(v.z - mm); v.w = __expf(v.w - mm);
    float s = v.x + v.y + v.z + v.w;
    #pragma unroll
    for (int o = 16; o; o >>= 1) s += __shfl_down_sync(0xFFFFFFFFu, s, o);
    if ((c & 31) == 0) sm[c >> 5] = s;
    __syncthreads();
    if (c == 0) {
        float S = 0.f;
        #pragma unroll
        for (int i = 0; i < 8; i++) S += sm[i];
        bs = 1.0f / S;
    }
    __syncthreads();
    float inv = bs;
    uint2 ho, lu;
    split2(v.x * inv, v.y * inv, ho.x, lu.x);
    split2(v.z * inv, v.w * inv, ho.y, lu.y);
    *(uint2*)(phi + row * T_ + c * 4) = ho;
    *(uint2*)(plo + row * T_ + c * 4) = lu;
}

// ---------------------------------------------------------------------------
// HMMA AV: per (b,h) O[1024,64] = P[1024,1024] * Vt[64,1024]^T
// ---------------------------------------------------------------------------
#define VAT_  (128 * RS_)
#define VBT_  (64 * RS_)
#define VSTG_ (2 * VAT_ + 2 * VBT_)
#define VSM_  (2 * VSTG_)

__global__ __launch_bounds__(256, 2)
void av_hmma(const __nv_bfloat16* __restrict__ Phi, const __nv_bfloat16* __restrict__ Plo,
             const __nv_bfloat16* __restrict__ Vth, const __nv_bfloat16* __restrict__ Vtl,
             __nv_bfloat16* __restrict__ Ohi, __nv_bfloat16* __restrict__ Olo) {
    extern __shared__ char sm[];
    uint32_t smb = smem_u32(sm);
    int tid = threadIdx.x, wid = tid >> 5, lane = tid & 31;
    int bh = blockIdx.y;
    int b = bh >> 4, h = bh & 15;
    size_t m0 = (size_t)blockIdx.x * 128;
    int wm = (wid & 1) * 64;
    int wn = (wid >> 1) * 16;

    const __nv_bfloat16* Ah = Phi + (size_t)bh * T_ * T_ + m0 * T_;
    const __nv_bfloat16* Al = Plo + (size_t)bh * T_ * T_ + m0 * T_;
    const __nv_bfloat16* Bh = Vth + (size_t)bh * DH_ * T_;
    const __nv_bfloat16* Bl = Vtl + (size_t)bh * DH_ * T_;

    auto load_stage = [&](int i, int s) {
        int k0 = i << 5;
        uint32_t sb = smb + s * VSTG_;
        #pragma unroll
        for (int t = 0; t < 2; t++) {
            int idx = tid + t * 256;
            int row = idx >> 2, ch = idx & 3;
            size_t go = (size_t)row * T_ + k0 + ch * 8;
            uint32_t so = row * RS_ + ch * 16;
            CP_ASYNC(sb + so,        Ah + go);
            CP_ASYNC(sb + VAT_ + so, Al + go);
        }
        {
            int row = tid >> 2, ch = tid & 3;
            size_t go = (size_t)row * T_ + k0 + ch * 8;
            uint32_t so = row * RS_ + ch * 16;
            CP_ASYNC(sb + 2 * VAT_ + so,        Bh + go);
            CP_ASYNC(sb + 2 * VAT_ + VBT_ + so, Bl + go);
        }
        CP_COMMIT();
    };

    float acc[4][2][4];
    #pragma unroll
    for (int a = 0; a < 4; a++)
        #pragma unroll
        for (int bq = 0; bq < 2; bq++)
            #pragma unroll
            for (int c = 0; c < 4; c++) acc[a][bq][c] = 0.f;

    int NC = T_ >> 5;
    load_stage(0, 0);

    int r16  = lane & 15;
    int ah16 = (lane >> 4) * 16;
    int brow = ((lane >> 4) & 1) * 8 + (lane & 7);
    int bo16 = ((lane >> 3) & 1) * 16;

    for (int i = 0; i < NC; i++) {
        int s = i & 1;
        if (i + 1 < NC) { load_stage(i + 1, s ^ 1); CP_WAIT(1); }
        else            { CP_WAIT(0); }
        __syncthreads();

        uint32_t sa = smb + s * VSTG_;
        #pragma unroll
        for (int j = 0; j < 2; j++) {
            uint32_t a_hi[4][4], a_lo[4][4];
            #pragma unroll
            for (int mt = 0; mt < 4; mt++) {
                uint32_t addr = sa + (wm + mt * 16 + r16) * RS_ + ah16 + j * 32;
                ldmatrix_x4(a_hi[mt], addr);
                ldmatrix_x4(a_lo[mt], addr + VAT_);
            }
            uint32_t b_hi[4], b_lo[4];
            {
                uint32_t addr = sa + 2 * VAT_ + (wn + brow) * RS_ + bo16 + j * 32;
                ldmatrix_x4(b_hi, addr);
                ldmatrix_x4(b_lo, addr + VBT_);
            }
            #pragma unroll
            for (int mt = 0; mt < 4; mt++)
                #pragma unroll
                for (int nt = 0; nt < 2; nt++)
                    mma_bf16(acc[mt][nt], a_hi[mt], &b_hi[nt * 2]);
            #pragma unroll
            for (int mt = 0; mt < 4; mt++)
                #pragma unroll
                for (int nt = 0; nt < 2; nt++)
                    mma_bf16(acc[mt][nt], a_hi[mt], &b_lo[nt * 2]);
            #pragma unroll
            for (int mt = 0; mt < 4; mt++)
                #pragma unroll
                for (int nt = 0; nt < 2; nt++)
                    mma_bf16(acc[mt][nt], a_lo[mt], &b_hi[nt * 2]);
        }
        __syncthreads();
    }

    int gr = lane >> 2;
    int gc = (lane & 3) * 2;
    #pragma unroll
    for (int mt = 0; mt < 4; mt++) {
        size_t row = m0 + wm + mt * 16 + gr;
        #pragma unroll
        for (int nt = 0; nt < 2; nt++) {
            int col = wn + nt * 8 + gc;
            size_t o0 = ((size_t)b * T_ + row) * D_ + h * DH_ + col;
            size_t o1 = ((size_t)b * T_ + row + 8) * D_ + h * DH_ + col;
            uint32_t h0, l0, h1, l1;
            split2(acc[mt][nt][0], acc[mt][nt][1], h0, l0);
            split2(acc[mt][nt][2], acc[mt][nt][3], h1, l1);
            *(uint32_t*)(Ohi + o0) = h0; *(uint32_t*)(Olo + o0) = l0;
            *(uint32_t*)(Ohi + o1) = h1; *(uint32_t*)(Olo + o1) = l1;
        }
    }
}

// ---------------------------------------------------------------------------
// Embedding
// ---------------------------------------------------------------------------
__global__ void embed_kernel(const int* __restrict__ tokens,
                             const float* __restrict__ embed,
                             const float* __restrict__ pos) {
    int row = blockIdx.x;
    int t = row & (T_ - 1);
    int tok = tokens[row];
    const float4* e = (const float4*)(embed + (size_t)tok * D_);
    const float4* p = (const float4*)(pos + (size_t)t * D_);
    float4* o = (float4*)(g_x + (size_t)row * D_);
    int c = threadIdx.x;
    float4 ev = e[c], pv = p[c];
    ev.x += pv.x; ev.y += pv.y; ev.z += pv.z; ev.w += pv.w;
    o[c] = ev;
}

// ---------------------------------------------------------------------------
// Kuramoto (bias cancels in softmax)
// ---------------------------------------------------------------------------
__global__ void kuramoto_kernel(const float* __restrict__ phase,
                                const float* __restrict__ freq,
                                const float* __restrict__ coupling,
                                const float* __restrict__ nbr_w,
                                const int* __restrict__ nbr_idx,
                                float* __restrict__ out_tail) {
    int i = threadIdx.x;
    if (i < L_ * H_) {
        int l = i / H_;
        float ph = phase[i];
        float sync = 0.0f;
        #pragma unroll
        for (int k = 0; k < KNB_; k++) {
            int id = nbr_idx[i * KNB_ + k];
            sync += nbr_w[i * KNB_ + k] * sinf(phase[l * H_ + id] - ph);
        }
        out_tail[i] = ph + DT_ * (freq[i] + coupling[l] * sync);
    }
}

// ---------------------------------------------------------------------------
// LayerNorm -> bf16 hi/lo
// ---------------------------------------------------------------------------
__global__ void ln_hilo(const float* __restrict__ x,
                        const float* __restrict__ g,
                        const float* __restrict__ b,
                        __nv_bfloat16* __restrict__ hi,
                        __nv_bfloat16* __restrict__ lo) {
    int row = blockIdx.x;
    int c = threadIdx.x;
    float4 v = ((const float4*)(x + (size_t)row * D_))[c];
    float s  = v.x + v.y + v.z + v.w;
    float s2 = v.x * v.x + v.y * v.y + v.z * v.z + v.w * v.w;
    #pragma unroll
    for (int o = 16; o; o >>= 1) {
        s  += __shfl_down_sync(0xFFFFFFFFu, s, o);
        s2 += __shfl_down_sync(0xFFFFFFFFu, s2, o);
    }
    __shared__ float ss[8], ss2[8];
    __shared__ float mu_s, rstd_s;
    if ((c & 31) == 0) { ss[c >> 5] = s; ss2[c >> 5] = s2; }
    __syncthreads();
    if (c == 0) {
        float S = 0.f, S2 = 0.f;
        #pragma unroll
        for (int i = 0; i < 8; i++) { S += ss[i]; S2 += ss2[i]; }
        float mu = S * (1.0f / D_);
        float var = S2 * (1.0f / D_) - mu * mu;
        mu_s = mu;
        rstd_s = rsqrtf(var + 1e-5f);
    }
    __syncthreads();
    float mu = mu_s, rstd = rstd_s;
    float4 gv = ((const float4*)g)[c];
    float4 bv = ((const float4*)b)[c];
    float o0 = (v.x - mu) * rstd * gv.x + bv.x;
    float o1 = (v.y - mu) * rstd * gv.y + bv.y;
    float o2 = (v.z - mu) * rstd * gv.z + bv.z;
    float o3 = (v.w - mu) * rstd * gv.w + bv.w;
    uint2 ho, lu;
    split2(o0, o1, ho.x, lu.x);
    split2(o2, o3, ho.y, lu.y);
    *(uint2*)(hi + (size_t)row * D_ + c * 4) = ho;
    *(uint2*)(lo + (size_t)row * D_ + c * 4) = lu;
}

// ---------------------------------------------------------------------------
// Host launcher
// ---------------------------------------------------------------------------
static inline void launch_conv(const float* src, __nv_bfloat16* hi, __nv_bfloat16* lo, size_t n) {
    int n4 = (int)(n / 4);
    conv_hilo<<<(n4 + 255) / 256, 256>>>(src, hi, lo, n4);
}

extern "C" void kernel_launch(void* const* d_in, const int* in_sizes, int n_in,
                              void* d_out, int out_size) {
    const int*   tokens   = (const int*)  d_in[0];
    const float* embed    = (const float*)d_in[1];
    const float* pos      = (const float*)d_in[2];
    const float* qkv_w    = (const float*)d_in[3];
    const float* qkv_b    = (const float*)d_in[4];
    const float* out_w    = (const float*)d_in[5];
    const float* out_b    = (const float*)d_in[6];
    const float* fc1_w    = (const float*)d_in[7];
    const float* fc1_b    = (const float*)d_in[8];
    const float* fc2_w    = (const float*)d_in[9];
    const float* fc2_b    = (const float*)d_in[10];
    const float* ln1_g    = (const float*)d_in[11];
    const float* ln1_b    = (const float*)d_in[12];
    const float* ln2_g    = (const float*)d_in[13];
    const float* ln2_b    = (const float*)d_in[14];
    const float* lnf_g    = (const float*)d_in[15];
    const float* lnf_b    = (const float*)d_in[16];
    const float* head_w   = (const float*)d_in[17];
    const float* head_b   = (const float*)d_in[18];
    const float* phase    = (const float*)d_in[19];
    const float* freq     = (const float*)d_in[20];
    const float* coupling = (const float*)d_in[21];
    const float* nbr_w    = (const float*)d_in[22];
    const int*   nbr_idx  = (const int*)  d_in[23];
    float* out = (float*)d_out;

    float* px;
    __nv_bfloat16 *pwh, *pwl, *pah, *pal, *pfh, *pfl, *pqh, *pql, *pph, *ppl, *pvh, *pvl;
    cudaGetSymbolAddress((void**)&px, g_x);
    cudaGetSymbolAddress((void**)&pwh, g_w_hi);
    cudaGetSymbolAddress((void**)&pwl, g_w_lo);
    cudaGetSymbolAddress((void**)&pah, g_act_hi);
    cudaGetSymbolAddress((void**)&pal, g_act_lo);
    cudaGetSymbolAddress((void**)&pfh, g_ff_hi);
    cudaGetSymbolAddress((void**)&pfl, g_ff_lo);
    cudaGetSymbolAddress((void**)&pqh, g_qkv_hi);
    cudaGetSymbolAddress((void**)&pql, g_qkv_lo);
    cudaGetSymbolAddress((void**)&pph, g_p_hi);
    cudaGetSymbolAddress((void**)&ppl, g_p_lo);
    cudaGetSymbolAddress((void**)&pvh, g_vt_hi);
    cudaGetSymbolAddress((void**)&pvl, g_vt_lo);

    cudaFuncSetAttribute((void*)hmma_gemm<256, 512, 1>, cudaFuncAttributeMaxDynamicSharedMemorySize, GSM256_);
    cudaFuncSetAttribute((void*)hmma_gemm<128, 256, 2>, cudaFuncAttributeMaxDynamicSharedMemorySize, GSM128_);
    cudaFuncSetAttribute(scores_hmma, cudaFuncAttributeMaxDynamicSharedMemorySize, SSM_);
    cudaFuncSetAttribute(av_hmma,     cudaFuncAttributeMaxDynamicSharedMemorySize, VSM_);

    const int M = B_ * T_;
    const float scale = 1.0f / 8.0f;

    // launch index 3 (ncu's consistent -s5 capture slot) = layer-0 QKV gemm
    embed_kernel<<<M, 256>>>(tokens, embed, pos);                          // 0
    launch_conv(qkv_w, pwh + W_QKV_OFF, pwl + W_QKV_OFF, W_QKV_N);         // 1
    ln_hilo<<<M, 256>>>(px, ln1_g, ln1_b, pah, pal);                       // 2
    hmma_gemm<256, 512, 1><<<dim3(3 * D_ / 128, M / 256), 512, GSM256_>>>( // 3 (profiled)
        pah, pal, pwh + W_QKV_OFF, pwl + W_QKV_OFF,
        qkv_b, nullptr, pqh, pql, 3 * D_, D_, 3);
    kuramoto_kernel<<<1, 128>>>(phase, freq, coupling, nbr_w, nbr_idx,
                                out + (size_t)B_ * T_ * V_);
    launch_conv(out_w,  pwh + W_OUT_OFF,  pwl + W_OUT_OFF,  W_OUT_N);
    launch_conv(fc1_w,  pwh + W_FC1_OFF,  pwl + W_FC1_OFF,  W_FC1_N);
    launch_conv(fc2_w,  pwh + W_FC2_OFF,  pwl + W_FC2_OFF,  W_FC2_N);
    launch_conv(head_w, pwh + W_HEAD_OFF, pwl + W_HEAD_OFF, W_HEAD_N);

    for (int l = 0; l < L_; l++) {
        if (l > 0) {
            ln_hilo<<<M, 256>>>(px, ln1_g + l * D_, ln1_b + l * D_, pah, pal);
            hmma_gemm<256, 512, 1><<<dim3(3 * D_ / 128, M / 256), 512, GSM256_>>>(
                pah, pal,
                pwh + W_QKV_OFF + (size_t)l * 3 * D_ * D_, pwl + W_QKV_OFF + (size_t)l * 3 * D_ * D_,
                qkv_b + l * 3 * D_, nullptr, pqh, pql, 3 * D_, D_, 3);
        }
        vt_kernel<<<dim3(T_ / 64, B_ * H_), 256>>>(pqh, pql, pvh, pvl);
        scores_hmma<<<dim3(T_ / 128, T_ / 128, B_ * H_), 256, SSM_>>>(pqh, pql, scale);
        softmax_kernel<<<B_ * H_ * T_, 256>>>(pph, ppl);
        av_hmma<<<dim3(T_ / 128, B_ * H_), 256, VSM_>>>(pph, ppl, pvh, pvl, pah, pal);
        // out-proj: BM=128 (grid 8x16, M-split)
        hmma_gemm<128, 256, 2><<<dim3(D_ / 128, M / 128), 256, GSM128_>>>(
            pah, pal,
            pwh + W_OUT_OFF + (size_t)l * D_ * D_, pwl + W_OUT_OFF + (size_t)l * D_ * D_,
            out_b + l * D_, px, nullptr, nullptr, D_, D_, 1);
        ln_hilo<<<M, 256>>>(px, ln2_g + l * D_, ln2_b + l * D_, pah, pal);
        hmma_gemm<256, 512, 1><<<dim3(FF_ / 128, M / 256), 512, GSM256_>>>(
            pah, pal,
            pwh + W_FC1_OFF + (size_t)l * FF_ * D_, pwl + W_FC1_OFF + (size_t)l * FF_ * D_,
            fc1_b + l * FF_, nullptr, pfh, pfl, FF_, D_, 2);
        hmma_gemm<128, 256, 2><<<dim3(D_ / 128, M / 128), 256, GSM128_>>>(
            pfh, pfl,
            pwh + W_FC2_OFF + (size_t)l * D_ * FF_, pwl + W_FC2_OFF + (size_t)l * D_ * FF_,
            fc2_b + l * D_, px, nullptr, nullptr, D_, FF_, 1);
    }

    ln_hilo<<<M, 256>>>(px, lnf_g, lnf_b, pah, pal);
    hmma_gemm<256, 512, 1><<<dim3(V_ / 128, M / 256), 512, GSM256_>>>(
        pah, pal, pwh + W_HEAD_OFF, pwl + W_HEAD_OFF,
        head_b, out, nullptr, nullptr, V_, D_, 0);
}

// round 16
// speedup vs baseline: 1.0728x; 1.0728x over previous
#include <cuda_runtime.h>
#include <cuda_bf16.h>
#include <math.h>
#include <stdint.h>

// Problem constants
#define L_   6
#define B_   2
#define T_   1024
#define D_   1024
#define H_   16
#define DH_  64
#define FF_  4096
#define V_   32000
#define KNB_ 4
#define DT_  0.1f

// ---------------------------------------------------------------------------
// Scratch
// ---------------------------------------------------------------------------
__device__ float g_x[B_ * T_ * D_];
__device__ float g_scores[(size_t)B_ * H_ * T_ * T_];

#define W_QKV_OFF  ((size_t)0)
#define W_QKV_N    ((size_t)L_ * 3 * D_ * D_)
#define W_OUT_OFF  (W_QKV_OFF + W_QKV_N)
#define W_OUT_N    ((size_t)L_ * D_ * D_)
#define W_FC1_OFF  (W_OUT_OFF + W_OUT_N)
#define W_FC1_N    ((size_t)L_ * FF_ * D_)
#define W_FC2_OFF  (W_FC1_OFF + W_FC1_N)
#define W_FC2_N    ((size_t)L_ * D_ * FF_)
#define W_HEAD_OFF (W_FC2_OFF + W_FC2_N)
#define W_HEAD_N   ((size_t)V_ * D_)
#define W_TOTAL    (W_HEAD_OFF + W_HEAD_N)

__device__ __nv_bfloat16 g_w_hi[W_TOTAL];
__device__ __nv_bfloat16 g_w_lo[W_TOTAL];
__device__ __nv_bfloat16 g_act_hi[B_ * T_ * D_];     // LN / attention outputs
__device__ __nv_bfloat16 g_act_lo[B_ * T_ * D_];
__device__ __nv_bfloat16 g_ff_hi[B_ * T_ * FF_];     // FC1 gelu output
__device__ __nv_bfloat16 g_ff_lo[B_ * T_ * FF_];
__device__ __nv_bfloat16 g_qkv_hi[B_ * T_ * 3 * D_]; // QKV proj, hi/lo
__device__ __nv_bfloat16 g_qkv_lo[B_ * T_ * 3 * D_];
__device__ __nv_bfloat16 g_p_hi[(size_t)B_ * H_ * T_ * T_];  // softmax probs
__device__ __nv_bfloat16 g_p_lo[(size_t)B_ * H_ * T_ * T_];
__device__ __nv_bfloat16 g_vt_hi[B_ * H_ * DH_ * T_];        // V transposed
__device__ __nv_bfloat16 g_vt_lo[B_ * H_ * DH_ * T_];

// ---------------------------------------------------------------------------
// helpers
// ---------------------------------------------------------------------------
__device__ __forceinline__ uint32_t smem_u32(const void* p) {
    uint32_t a;
    asm("{ .reg .u64 t; cvta.to.shared.u64 t, %1; cvt.u32.u64 %0, t; }" : "=r"(a) : "l"(p));
    return a;
}
__device__ __forceinline__ void ldmatrix_x4(uint32_t* r, uint32_t addr) {
    asm volatile("ldmatrix.sync.aligned.m8n8.x4.shared.b16 {%0,%1,%2,%3},[%4];"
                 : "=r"(r[0]), "=r"(r[1]), "=r"(r[2]), "=r"(r[3]) : "r"(addr));
}
__device__ __forceinline__ void mma_bf16(float* c, const uint32_t* a, const uint32_t* b) {
    asm volatile(
        "mma.sync.aligned.m16n8k16.row.col.f32.bf16.bf16.f32 "
        "{%0,%1,%2,%3},{%4,%5,%6,%7},{%8,%9},{%0,%1,%2,%3};"
        : "+f"(c[0]), "+f"(c[1]), "+f"(c[2]), "+f"(c[3])
        : "r"(a[0]), "r"(a[1]), "r"(a[2]), "r"(a[3]), "r"(b[0]), "r"(b[1]));
}
#define CP_ASYNC(dst, src) \
    asm volatile("cp.async.cg.shared.global [%0],[%1],16;" :: "r"(dst), "l"(src))
#define CP_COMMIT() asm volatile("cp.async.commit_group;")
#define CP_WAIT(N)  asm volatile("cp.async.wait_group %0;" :: "n"(N))

__device__ __forceinline__ void split2(float x, float y, uint32_t& h, uint32_t& l) {
    __nv_bfloat16 hx = __float2bfloat16(x);
    __nv_bfloat16 hy = __float2bfloat16(y);
    __nv_bfloat16 lx = __float2bfloat16(x - __bfloat162float(hx));
    __nv_bfloat16 ly = __float2bfloat16(y - __bfloat162float(hy));
    h = (uint32_t)__bfloat16_as_ushort(hx) | ((uint32_t)__bfloat16_as_ushort(hy) << 16);
    l = (uint32_t)__bfloat16_as_ushort(lx) | ((uint32_t)__bfloat16_as_ushort(ly) << 16);
}
__device__ __forceinline__ float gelu_f(float t) {
    float u = 0.7978845608028654f * (t + 0.044715f * t * t * t);
    return 0.5f * t * (1.0f + tanhf(u));
}

// ---------------------------------------------------------------------------
// fp32 -> bf16 hi/lo split (weights only)
// ---------------------------------------------------------------------------
__global__ void conv_hilo(const float* __restrict__ src,
                          __nv_bfloat16* __restrict__ hi,
                          __nv_bfloat16* __restrict__ lo, int n4) {
    int i = blockIdx.x * 256 + threadIdx.x;
    if (i >= n4) return;
    float4 v = ((const float4*)src)[i];
    uint2 ho, lu;
    split2(v.x, v.y, ho.x, lu.x);
    split2(v.z, v.w, ho.y, lu.y);
    *(uint2*)(hi + (size_t)4 * i) = ho;
    *(uint2*)(lo + (size_t)4 * i) = lu;
}

// ---------------------------------------------------------------------------
// HMMA NT-GEMM: 128x128 CTA tile, BK=32, 2-stage cp.async, regs capped at 128
// (2 CTAs/SM).  modes: 0 bias+store, 1 bias+add+store, 2 bias+gelu->hi/lo,
// 3 bias->hi/lo (no gelu).   [round-11 verified optimum: tensor 48.5%]
// ---------------------------------------------------------------------------
#define RS_   80
#define AT_   (128 * RS_)          // 10240 bytes per operand tile
#define STG_  (4 * AT_)            // 40960 per stage
#define GSM_  (2 * STG_)           // 81920

__global__ __launch_bounds__(256, 2)
void hmma_gemm(const __nv_bfloat16* __restrict__ Ahi, const __nv_bfloat16* __restrict__ Alo,
               const __nv_bfloat16* __restrict__ Bhi, const __nv_bfloat16* __restrict__ Blo,
               const float* __restrict__ bias, float* __restrict__ C,
               __nv_bfloat16* __restrict__ Ohi, __nv_bfloat16* __restrict__ Olo,
               int N, int Kd, int mode) {
    extern __shared__ char sm[];
    uint32_t smb = smem_u32(sm);
    int tid = threadIdx.x, wid = tid >> 5, lane = tid & 31;
    size_t m0 = (size_t)blockIdx.y * 128;
    size_t n0 = (size_t)blockIdx.x * 128;
    int wm = (wid & 1) * 64;
    int wn = (wid >> 1) * 32;

    const __nv_bfloat16* Ah = Ahi + m0 * (size_t)Kd;
    const __nv_bfloat16* Al = Alo + m0 * (size_t)Kd;
    const __nv_bfloat16* Bh = Bhi + n0 * (size_t)Kd;
    const __nv_bfloat16* Bl = Blo + n0 * (size_t)Kd;

    auto load_stage = [&](int i, int s) {
        int k0 = i << 5;
        uint32_t sb = smb + s * STG_;
        #pragma unroll
        for (int t = 0; t < 2; t++) {
            int idx = tid + t * 256;
            int row = idx >> 2, ch = idx & 3;
            size_t go = (size_t)row * Kd + k0 + ch * 8;
            uint32_t so = row * RS_ + ch * 16;
            CP_ASYNC(sb + so,            Ah + go);
            CP_ASYNC(sb + AT_ + so,      Al + go);
            CP_ASYNC(sb + 2 * AT_ + so,  Bh + go);
            CP_ASYNC(sb + 3 * AT_ + so,  Bl + go);
        }
        CP_COMMIT();
    };

    float acc[4][4][4];
    #pragma unroll
    for (int a = 0; a < 4; a++)
        #pragma unroll
        for (int b = 0; b < 4; b++)
            #pragma unroll
            for (int c = 0; c < 4; c++) acc[a][b][c] = 0.f;

    int NC = Kd >> 5;
    load_stage(0, 0);

    int r16  = lane & 15;
    int ah16 = (lane >> 4) * 16;
    int brow = ((lane >> 4) & 1) * 8 + (lane & 7);
    int bo16 = ((lane >> 3) & 1) * 16;

    for (int i = 0; i < NC; i++) {
        int s = i & 1;
        if (i + 1 < NC) { load_stage(i + 1, s ^ 1); CP_WAIT(1); }
        else            { CP_WAIT(0); }
        __syncthreads();

        uint32_t sa = smb + s * STG_;
        #pragma unroll
        for (int j = 0; j < 2; j++) {
            uint32_t a_hi[4][4], a_lo[4][4];
            #pragma unroll
            for (int mt = 0; mt < 4; mt++) {
                uint32_t addr = sa + (wm + mt * 16 + r16) * RS_ + ah16 + j * 32;
                ldmatrix_x4(a_hi[mt], addr);
                ldmatrix_x4(a_lo[mt], addr + AT_);
            }
            uint32_t b_hi[2][4], b_lo[2][4];
            #pragma unroll
            for (int p = 0; p < 2; p++) {
                uint32_t addr = sa + 2 * AT_ + (wn + p * 16 + brow) * RS_ + bo16 + j * 32;
                ldmatrix_x4(b_hi[p], addr);
                ldmatrix_x4(b_lo[p], addr + AT_);
            }
            #pragma unroll
            for (int mt = 0; mt < 4; mt++)
                #pragma unroll
                for (int nt = 0; nt < 4; nt++)
                    mma_bf16(acc[mt][nt], a_hi[mt], &b_hi[nt >> 1][(nt & 1) * 2]);
            #pragma unroll
            for (int mt = 0; mt < 4; mt++)
                #pragma unroll
                for (int nt = 0; nt < 4; nt++)
                    mma_bf16(acc[mt][nt], a_hi[mt], &b_lo[nt >> 1][(nt & 1) * 2]);
            #pragma unroll
            for (int mt = 0; mt < 4; mt++)
                #pragma unroll
                for (int nt = 0; nt < 4; nt++)
                    mma_bf16(acc[mt][nt], a_lo[mt], &b_hi[nt >> 1][(nt & 1) * 2]);
        }
        __syncthreads();
    }

    int gr = lane >> 2;
    int gc = (lane & 3) * 2;
    #pragma unroll
    for (int mt = 0; mt < 4; mt++) {
        size_t row = m0 + wm + mt * 16 + gr;
        #pragma unroll
        for (int nt = 0; nt < 4; nt++) {
            size_t col = n0 + wn + nt * 8 + gc;
            float2 bv = *(const float2*)(bias + col);
            float v00 = acc[mt][nt][0] + bv.x, v01 = acc[mt][nt][1] + bv.y;
            float v10 = acc[mt][nt][2] + bv.x, v11 = acc[mt][nt][3] + bv.y;
            size_t o0 = row * (size_t)N + col;
            size_t o1 = (row + 8) * (size_t)N + col;
            if (mode >= 2) {
                if (mode == 2) {
                    v00 = gelu_f(v00); v01 = gelu_f(v01);
                    v10 = gelu_f(v10); v11 = gelu_f(v11);
                }
                uint32_t h0, l0, h1, l1;
                split2(v00, v01, h0, l0);
                split2(v10, v11, h1, l1);
                *(uint32_t*)(Ohi + o0) = h0; *(uint32_t*)(Olo + o0) = l0;
                *(uint32_t*)(Ohi + o1) = h1; *(uint32_t*)(Olo + o1) = l1;
            } else {
                if (mode == 1) {
                    float2 a0 = *(float2*)(C + o0), a1 = *(float2*)(C + o1);
                    v00 += a0.x; v01 += a0.y; v10 += a1.x; v11 += a1.y;
                }
                float2 w0 = {v00, v01}, w1 = {v10, v11};
                *(float2*)(C + o0) = w0;
                *(float2*)(C + o1) = w1;
            }
        }
    }
}

// ---------------------------------------------------------------------------
// HMMA attention scores: per (b,h) 128x128 tile, K = DH = 64 in one stage.
// ---------------------------------------------------------------------------
#define SRS_  144
#define SAT_  (128 * SRS_)
#define SSM_  (4 * SAT_)

__global__ __launch_bounds__(256, 2)
void scores_hmma(const __nv_bfloat16* __restrict__ qh,
                 const __nv_bfloat16* __restrict__ ql, float scale) {
    extern __shared__ char sm[];
    uint32_t smb = smem_u32(sm);
    int tid = threadIdx.x, wid = tid >> 5, lane = tid & 31;
    int bh = blockIdx.z;
    int b = bh >> 4, h = bh & 15;
    size_t m0 = (size_t)blockIdx.y * 128;
    size_t n0 = (size_t)blockIdx.x * 128;
    int wm = (wid & 1) * 64;
    int wn = (wid >> 1) * 32;

    const __nv_bfloat16* Ah = qh + ((size_t)b * T_ + m0) * (3 * D_) + h * DH_;
    const __nv_bfloat16* Al = ql + ((size_t)b * T_ + m0) * (3 * D_) + h * DH_;
    const __nv_bfloat16* Bh = qh + ((size_t)b * T_ + n0) * (3 * D_) + D_ + h * DH_;
    const __nv_bfloat16* Bl = ql + ((size_t)b * T_ + n0) * (3 * D_) + D_ + h * DH_;

    const __nv_bfloat16* srcs[4] = {Ah, Al, Bh, Bl};
    #pragma unroll
    for (int tile = 0; tile < 4; tile++) {
        #pragma unroll
        for (int t = 0; t < 4; t++) {
            int idx = tid + t * 256;
            int r = idx >> 3, ch = idx & 7;
            CP_ASYNC(smb + tile * SAT_ + r * SRS_ + ch * 16,
                     srcs[tile] + (size_t)r * (3 * D_) + ch * 8);
        }
    }
    CP_COMMIT();
    CP_WAIT(0);
    __syncthreads();

    float acc[4][4][4];
    #pragma unroll
    for (int a = 0; a < 4; a++)
        #pragma unroll
        for (int bq = 0; bq < 4; bq++)
            #pragma unroll
            for (int c = 0; c < 4; c++) acc[a][bq][c] = 0.f;

    int r16  = lane & 15;
    int ah16 = (lane >> 4) * 16;
    int brow = ((lane >> 4) & 1) * 8 + (lane & 7);
    int bo16 = ((lane >> 3) & 1) * 16;

    #pragma unroll
    for (int j = 0; j < 4; j++) {
        uint32_t a_hi[4][4], a_lo[4][4];
        #pragma unroll
        for (int mt = 0; mt < 4; mt++) {
            uint32_t addr = smb + (wm + mt * 16 + r16) * SRS_ + ah16 + j * 32;
            ldmatrix_x4(a_hi[mt], addr);
            ldmatrix_x4(a_lo[mt], addr + SAT_);
        }
        uint32_t b_hi[2][4], b_lo[2][4];
        #pragma unroll
        for (int p = 0; p < 2; p++) {
            uint32_t addr = smb + 2 * SAT_ + (wn + p * 16 + brow) * SRS_ + bo16 + j * 32;
            ldmatrix_x4(b_hi[p], addr);
            ldmatrix_x4(b_lo[p], addr + SAT_);
        }
        #pragma unroll
        for (int mt = 0; mt < 4; mt++)
            #pragma unroll
            for (int nt = 0; nt < 4; nt++)
                mma_bf16(acc[mt][nt], a_hi[mt], &b_hi[nt >> 1][(nt & 1) * 2]);
        #pragma unroll
        for (int mt = 0; mt < 4; mt++)
            #pragma unroll
            for (int nt = 0; nt < 4; nt++)
                mma_bf16(acc[mt][nt], a_hi[mt], &b_lo[nt >> 1][(nt & 1) * 2]);
        #pragma unroll
        for (int mt = 0; mt < 4; mt++)
            #pragma unroll
            for (int nt = 0; nt < 4; nt++)
                mma_bf16(acc[mt][nt], a_lo[mt], &b_hi[nt >> 1][(nt & 1) * 2]);
    }

    float* srow = g_scores + (size_t)bh * T_ * T_;
    int gr = lane >> 2;
    int gc = (lane & 3) * 2;
    #pragma unroll
    for (int mt = 0; mt < 4; mt++) {
        size_t row = m0 + wm + mt * 16 + gr;
        #pragma unroll
        for (int nt = 0; nt < 4; nt++) {
            size_t col = n0 + wn + nt * 8 + gc;
            float2 w0 = {acc[mt][nt][0] * scale, acc[mt][nt][1] * scale};
            float2 w1 = {acc[mt][nt][2] * scale, acc[mt][nt][3] * scale};
            *(float2*)(srow + row * T_ + col) = w0;
            *(float2*)(srow + (row + 8) * T_ + col) = w1;
        }
    }
}

// ---------------------------------------------------------------------------
// V transpose: [b,k,h,dh] hi/lo -> [b,h,dh,k] hi/lo
// ---------------------------------------------------------------------------
__global__ void vt_kernel(const __nv_bfloat16* __restrict__ qh,
                          const __nv_bfloat16* __restrict__ ql,
                          __nv_bfloat16* __restrict__ vth,
                          __nv_bfloat16* __restrict__ vtl) {
    __shared__ __align__(16) __nv_bfloat16 th[64][72];
    __shared__ __align__(16) __nv_bfloat16 tl[64][72];
    int bh = blockIdx.y;
    int b = bh >> 4, h = bh & 15;
    int k0 = blockIdx.x * 64;
    int tid = threadIdx.x;
    const __nv_bfloat16* inh = qh + ((size_t)b * T_ + k0) * (3 * D_) + 2 * D_ + h * DH_;
    const __nv_bfloat16* inl = ql + ((size_t)b * T_ + k0) * (3 * D_) + 2 * D_ + h * DH_;
    #pragma unroll
    for (int t = 0; t < 2; t++) {
        int idx = tid + t * 256;
        int r = idx >> 3, c = idx & 7;
        *(uint4*)&th[r][c * 8] = *(const uint4*)(inh + (size_t)r * (3 * D_) + c * 8);
        *(uint4*)&tl[r][c * 8] = *(const uint4*)(inl + (size_t)r * (3 * D_) + c * 8);
    }
    __syncthreads();
    #pragma unroll
    for (int t = 0; t < 2; t++) {
        int idx = tid + t * 256;
        int dh = idx >> 3, c = idx & 7;
        __nv_bfloat16 bh8[8], bl8[8];
        #pragma unroll
        for (int u = 0; u < 8; u++) { bh8[u] = th[c * 8 + u][dh]; bl8[u] = tl[c * 8 + u][dh]; }
        size_t off = ((size_t)bh * DH_ + dh) * T_ + k0 + c * 8;
        *(uint4*)(vth + off) = *(uint4*)bh8;
        *(uint4*)(vtl + off) = *(uint4*)bl8;
    }
}

// ---------------------------------------------------------------------------
// Row softmax over T=1024: fp32 scores -> P bf16 hi/lo
// ---------------------------------------------------------------------------
__global__ void softmax_kernel(__nv_bfloat16* __restrict__ phi,
                               __nv_bfloat16* __restrict__ plo) {
    size_t row = blockIdx.x;
    int c = threadIdx.x;
    const float4* rp = (const float4*)(g_scores + row * T_);
    float4 v = rp[c];
    float m = fmaxf(fmaxf(v.x, v.y), fmaxf(v.z, v.w));
    #pragma unroll
    for (int o = 16; o; o >>= 1) m = fmaxf(m, __shfl_down_sync(0xFFFFFFFFu, m, o));
    __shared__ float sm[8];
    __shared__ float bm, bs;
    if ((c & 31) == 0) sm[c >> 5] = m;
    __syncthreads();
    if (c == 0) {
        float mm = sm[0];
        #pragma unroll
        for (int i = 1; i < 8; i++) mm = fmaxf(mm, sm[i]);
        bm = mm;
    }
    __syncthreads();
    float mm = bm;
    v.x = __expf(v.x - mm); v.y = __expf(v.y - mm);
    v.z = __expf(v.z - mm); v.w = __expf(v.w - mm);
    float s = v.x + v.y + v.z + v.w;
    #pragma unroll
    for (int o = 16; o; o >>= 1) s += __shfl_down_sync(0xFFFFFFFFu, s, o);
    if ((c & 31) == 0) sm[c >> 5] = s;
    __syncthreads();
    if (c == 0) {
        float S = 0.f;
        #pragma unroll
        for (int i = 0; i < 8; i++) S += sm[i];
        bs = 1.0f / S;
    }
    __syncthreads();
    float inv = bs;
    uint2 ho, lu;
    split2(v.x * inv, v.y * inv, ho.x, lu.x);
    split2(v.z * inv, v.w * inv, ho.y, lu.y);
    *(uint2*)(phi + row * T_ + c * 4) = ho;
    *(uint2*)(plo + row * T_ + c * 4) = lu;
}

// ---------------------------------------------------------------------------
// HMMA AV: per (b,h) O[1024,64] = P[1024,1024] * Vt[64,1024]^T
// ---------------------------------------------------------------------------
#define VAT_  (128 * RS_)
#define VBT_  (64 * RS_)
#define VSTG_ (2 * VAT_ + 2 * VBT_)
#define VSM_  (2 * VSTG_)

__global__ __launch_bounds__(256, 2)
void av_hmma(const __nv_bfloat16* __restrict__ Phi, const __nv_bfloat16* __restrict__ Plo,
             const __nv_bfloat16* __restrict__ Vth, const __nv_bfloat16* __restrict__ Vtl,
             __nv_bfloat16* __restrict__ Ohi, __nv_bfloat16* __restrict__ Olo) {
    extern __shared__ char sm[];
    uint32_t smb = smem_u32(sm);
    int tid = threadIdx.x, wid = tid >> 5, lane = tid & 31;
    int bh = blockIdx.y;
    int b = bh >> 4, h = bh & 15;
    size_t m0 = (size_t)blockIdx.x * 128;
    int wm = (wid & 1) * 64;
    int wn = (wid >> 1) * 16;

    const __nv_bfloat16* Ah = Phi + (size_t)bh * T_ * T_ + m0 * T_;
    const __nv_bfloat16* Al = Plo + (size_t)bh * T_ * T_ + m0 * T_;
    const __nv_bfloat16* Bh = Vth + (size_t)bh * DH_ * T_;
    const __nv_bfloat16* Bl = Vtl + (size_t)bh * DH_ * T_;

    auto load_stage = [&](int i, int s) {
        int k0 = i << 5;
        uint32_t sb = smb + s * VSTG_;
        #pragma unroll
        for (int t = 0; t < 2; t++) {
            int idx = tid + t * 256;
            int row = idx >> 2, ch = idx & 3;
            size_t go = (size_t)row * T_ + k0 + ch * 8;
            uint32_t so = row * RS_ + ch * 16;
            CP_ASYNC(sb + so,        Ah + go);
            CP_ASYNC(sb + VAT_ + so, Al + go);
        }
        {
            int row = tid >> 2, ch = tid & 3;
            size_t go = (size_t)row * T_ + k0 + ch * 8;
            uint32_t so = row * RS_ + ch * 16;
            CP_ASYNC(sb + 2 * VAT_ + so,        Bh + go);
            CP_ASYNC(sb + 2 * VAT_ + VBT_ + so, Bl + go);
        }
        CP_COMMIT();
    };

    float acc[4][2][4];
    #pragma unroll
    for (int a = 0; a < 4; a++)
        #pragma unroll
        for (int bq = 0; bq < 2; bq++)
            #pragma unroll
            for (int c = 0; c < 4; c++) acc[a][bq][c] = 0.f;

    int NC = T_ >> 5;
    load_stage(0, 0);

    int r16  = lane & 15;
    int ah16 = (lane >> 4) * 16;
    int brow = ((lane >> 4) & 1) * 8 + (lane & 7);
    int bo16 = ((lane >> 3) & 1) * 16;

    for (int i = 0; i < NC; i++) {
        int s = i & 1;
        if (i + 1 < NC) { load_stage(i + 1, s ^ 1); CP_WAIT(1); }
        else            { CP_WAIT(0); }
        __syncthreads();

        uint32_t sa = smb + s * VSTG_;
        #pragma unroll
        for (int j = 0; j < 2; j++) {
            uint32_t a_hi[4][4], a_lo[4][4];
            #pragma unroll
            for (int mt = 0; mt < 4; mt++) {
                uint32_t addr = sa + (wm + mt * 16 + r16) * RS_ + ah16 + j * 32;
                ldmatrix_x4(a_hi[mt], addr);
                ldmatrix_x4(a_lo[mt], addr + VAT_);
            }
            uint32_t b_hi[4], b_lo[4];
            {
                uint32_t addr = sa + 2 * VAT_ + (wn + brow) * RS_ + bo16 + j * 32;
                ldmatrix_x4(b_hi, addr);
                ldmatrix_x4(b_lo, addr + VBT_);
            }
            #pragma unroll
            for (int mt = 0; mt < 4; mt++)
                #pragma unroll
                for (int nt = 0; nt < 2; nt++)
                    mma_bf16(acc[mt][nt], a_hi[mt], &b_hi[nt * 2]);
            #pragma unroll
            for (int mt = 0; mt < 4; mt++)
                #pragma unroll
                for (int nt = 0; nt < 2; nt++)
                    mma_bf16(acc[mt][nt], a_hi[mt], &b_lo[nt * 2]);
            #pragma unroll
            for (int mt = 0; mt < 4; mt++)
                #pragma unroll
                for (int nt = 0; nt < 2; nt++)
                    mma_bf16(acc[mt][nt], a_lo[mt], &b_hi[nt * 2]);
        }
        __syncthreads();
    }

    int gr = lane >> 2;
    int gc = (lane & 3) * 2;
    #pragma unroll
    for (int mt = 0; mt < 4; mt++) {
        size_t row = m0 + wm + mt * 16 + gr;
        #pragma unroll
        for (int nt = 0; nt < 2; nt++) {
            int col = wn + nt * 8 + gc;
            size_t o0 = ((size_t)b * T_ + row) * D_ + h * DH_ + col;
            size_t o1 = ((size_t)b * T_ + row + 8) * D_ + h * DH_ + col;
            uint32_t h0, l0, h1, l1;
            split2(acc[mt][nt][0], acc[mt][nt][1], h0, l0);
            split2(acc[mt][nt][2], acc[mt][nt][3], h1, l1);
            *(uint32_t*)(Ohi + o0) = h0; *(uint32_t*)(Olo + o0) = l0;
            *(uint32_t*)(Ohi + o1) = h1; *(uint32_t*)(Olo + o1) = l1;
        }
    }
}

// ---------------------------------------------------------------------------
// Embedding
// ---------------------------------------------------------------------------
__global__ void embed_kernel(const int* __restrict__ tokens,
                             const float* __restrict__ embed,
                             const float* __restrict__ pos) {
    int row = blockIdx.x;
    int t = row & (T_ - 1);
    int tok = tokens[row];
    const float4* e = (const float4*)(embed + (size_t)tok * D_);
    const float4* p = (const float4*)(pos + (size_t)t * D_);
    float4* o = (float4*)(g_x + (size_t)row * D_);
    int c = threadIdx.x;
    float4 ev = e[c], pv = p[c];
    ev.x += pv.x; ev.y += pv.y; ev.z += pv.z; ev.w += pv.w;
    o[c] = ev;
}

// ---------------------------------------------------------------------------
// Kuramoto (bias cancels in softmax)
// ---------------------------------------------------------------------------
__global__ void kuramoto_kernel(const float* __restrict__ phase,
                                const float* __restrict__ freq,
                                const float* __restrict__ coupling,
                                const float* __restrict__ nbr_w,
                                const int* __restrict__ nbr_idx,
                                float* __restrict__ out_tail) {
    int i = threadIdx.x;
    if (i < L_ * H_) {
        int l = i / H_;
        float ph = phase[i];
        float sync = 0.0f;
        #pragma unroll
        for (int k = 0; k < KNB_; k++) {
            int id = nbr_idx[i * KNB_ + k];
            sync += nbr_w[i * KNB_ + k] * sinf(phase[l * H_ + id] - ph);
        }
        out_tail[i] = ph + DT_ * (freq[i] + coupling[l] * sync);
    }
}

// ---------------------------------------------------------------------------
// LayerNorm -> bf16 hi/lo
// ---------------------------------------------------------------------------
__global__ void ln_hilo(const float* __restrict__ x,
                        const float* __restrict__ g,
                        const float* __restrict__ b,
                        __nv_bfloat16* __restrict__ hi,
                        __nv_bfloat16* __restrict__ lo) {
    int row = blockIdx.x;
    int c = threadIdx.x;
    float4 v = ((const float4*)(x + (size_t)row * D_))[c];
    float s  = v.x + v.y + v.z + v.w;
    float s2 = v.x * v.x + v.y * v.y + v.z * v.z + v.w * v.w;
    #pragma unroll
    for (int o = 16; o; o >>= 1) {
        s  += __shfl_down_sync(0xFFFFFFFFu, s, o);
        s2 += __shfl_down_sync(0xFFFFFFFFu, s2, o);
    }
    __shared__ float ss[8], ss2[8];
    __shared__ float mu_s, rstd_s;
    if ((c & 31) == 0) { ss[c >> 5] = s; ss2[c >> 5] = s2; }
    __syncthreads();
    if (c == 0) {
        float S = 0.f, S2 = 0.f;
        #pragma unroll
        for (int i = 0; i < 8; i++) { S += ss[i]; S2 += ss2[i]; }
        float mu = S * (1.0f / D_);
        float var = S2 * (1.0f / D_) - mu * mu;
        mu_s = mu;
        rstd_s = rsqrtf(var + 1e-5f);
    }
    __syncthreads();
    float mu = mu_s, rstd = rstd_s;
    float4 gv = ((const float4*)g)[c];
    float4 bv = ((const float4*)b)[c];
    float o0 = (v.x - mu) * rstd * gv.x + bv.x;
    float o1 = (v.y - mu) * rstd * gv.y + bv.y;
    float o2 = (v.z - mu) * rstd * gv.z + bv.z;
    float o3 = (v.w - mu) * rstd * gv.w + bv.w;
    uint2 ho, lu;
    split2(o0, o1, ho.x, lu.x);
    split2(o2, o3, ho.y, lu.y);
    *(uint2*)(hi + (size_t)row * D_ + c * 4) = ho;
    *(uint2*)(lo + (size_t)row * D_ + c * 4) = lu;
}

// ---------------------------------------------------------------------------
// Host launcher
// ---------------------------------------------------------------------------
static inline void launch_conv(const float* src, __nv_bfloat16* hi, __nv_bfloat16* lo, size_t n) {
    int n4 = (int)(n / 4);
    conv_hilo<<<(n4 + 255) / 256, 256>>>(src, hi, lo, n4);
}

extern "C" void kernel_launch(void* const* d_in, const int* in_sizes, int n_in,
                              void* d_out, int out_size) {
    const int*   tokens   = (const int*)  d_in[0];
    const float* embed    = (const float*)d_in[1];
    const float* pos      = (const float*)d_in[2];
    const float* qkv_w    = (const float*)d_in[3];
    const float* qkv_b    = (const float*)d_in[4];
    const float* out_w    = (const float*)d_in[5];
    const float* out_b    = (const float*)d_in[6];
    const float* fc1_w    = (const float*)d_in[7];
    const float* fc1_b    = (const float*)d_in[8];
    const float* fc2_w    = (const float*)d_in[9];
    const float* fc2_b    = (const float*)d_in[10];
    const float* ln1_g    = (const float*)d_in[11];
    const float* ln1_b    = (const float*)d_in[12];
    const float* ln2_g    = (const float*)d_in[13];
    const float* ln2_b    = (const float*)d_in[14];
    const float* lnf_g    = (const float*)d_in[15];
    const float* lnf_b    = (const float*)d_in[16];
    const float* head_w   = (const float*)d_in[17];
    const float* head_b   = (const float*)d_in[18];
    const float* phase    = (const float*)d_in[19];
    const float* freq     = (const float*)d_in[20];
    const float* coupling = (const float*)d_in[21];
    const float* nbr_w    = (const float*)d_in[22];
    const int*   nbr_idx  = (const int*)  d_in[23];
    float* out = (float*)d_out;

    float* px;
    __nv_bfloat16 *pwh, *pwl, *pah, *pal, *pfh, *pfl, *pqh, *pql, *pph, *ppl, *pvh, *pvl;
    cudaGetSymbolAddress((void**)&px, g_x);
    cudaGetSymbolAddress((void**)&pwh, g_w_hi);
    cudaGetSymbolAddress((void**)&pwl, g_w_lo);
    cudaGetSymbolAddress((void**)&pah, g_act_hi);
    cudaGetSymbolAddress((void**)&pal, g_act_lo);
    cudaGetSymbolAddress((void**)&pfh, g_ff_hi);
    cudaGetSymbolAddress((void**)&pfl, g_ff_lo);
    cudaGetSymbolAddress((void**)&pqh, g_qkv_hi);
    cudaGetSymbolAddress((void**)&pql, g_qkv_lo);
    cudaGetSymbolAddress((void**)&pph, g_p_hi);
    cudaGetSymbolAddress((void**)&ppl, g_p_lo);
    cudaGetSymbolAddress((void**)&pvh, g_vt_hi);
    cudaGetSymbolAddress((void**)&pvl, g_vt_lo);

    cudaFuncSetAttribute(hmma_gemm,   cudaFuncAttributeMaxDynamicSharedMemorySize, GSM_);
    cudaFuncSetAttribute(scores_hmma, cudaFuncAttributeMaxDynamicSharedMemorySize, SSM_);
    cudaFuncSetAttribute(av_hmma,     cudaFuncAttributeMaxDynamicSharedMemorySize, VSM_);

    const int M = B_ * T_;
    const float scale = 1.0f / 8.0f;

    // launch index 3 (ncu's consistent -s5 capture slot) = layer-0 QKV gemm
    embed_kernel<<<M, 256>>>(tokens, embed, pos);                          // 0
    launch_conv(qkv_w, pwh + W_QKV_OFF, pwl + W_QKV_OFF, W_QKV_N);         // 1
    ln_hilo<<<M, 256>>>(px, ln1_g, ln1_b, pah, pal);                       // 2
    hmma_gemm<<<dim3(3 * D_ / 128, M / 128), 256, GSM_>>>(                 // 3 (profiled)
        pah, pal, pwh + W_QKV_OFF, pwl + W_QKV_OFF,
        qkv_b, nullptr, pqh, pql, 3 * D_, D_, 3);
    kuramoto_kernel<<<1, 128>>>(phase, freq, coupling, nbr_w, nbr_idx,
                                out + (size_t)B_ * T_ * V_);
    launch_conv(out_w,  pwh + W_OUT_OFF,  pwl + W_OUT_OFF,  W_OUT_N);
    launch_conv(fc1_w,  pwh + W_FC1_OFF,  pwl + W_FC1_OFF,  W_FC1_N);
    launch_conv(fc2_w,  pwh + W_FC2_OFF,  pwl + W_FC2_OFF,  W_FC2_N);
    launch_conv(head_w, pwh + W_HEAD_OFF, pwl + W_HEAD_OFF, W_HEAD_N);

    for (int l = 0; l < L_; l++) {
        if (l > 0) {
            ln_hilo<<<M, 256>>>(px, ln1_g + l * D_, ln1_b + l * D_, pah, pal);
            hmma_gemm<<<dim3(3 * D_ / 128, M / 128), 256, GSM_>>>(
                pah, pal,
                pwh + W_QKV_OFF + (size_t)l * 3 * D_ * D_, pwl + W_QKV_OFF + (size_t)l * 3 * D_ * D_,
                qkv_b + l * 3 * D_, nullptr, pqh, pql, 3 * D_, D_, 3);
        }
        vt_kernel<<<dim3(T_ / 64, B_ * H_), 256>>>(pqh, pql, pvh, pvl);
        scores_hmma<<<dim3(T_ / 128, T_ / 128, B_ * H_), 256, SSM_>>>(pqh, pql, scale);
        softmax_kernel<<<B_ * H_ * T_, 256>>>(pph, ppl);
        av_hmma<<<dim3(T_ / 128, B_ * H_), 256, VSM_>>>(pph, ppl, pvh, pvl, pah, pal);
        hmma_gemm<<<dim3(D_ / 128, M / 128), 256, GSM_>>>(
            pah, pal,
            pwh + W_OUT_OFF + (size_t)l * D_ * D_, pwl + W_OUT_OFF + (size_t)l * D_ * D_,
            out_b + l * D_, px, nullptr, nullptr, D_, D_, 1);
        ln_hilo<<<M, 256>>>(px, ln2_g + l * D_, ln2_b + l * D_, pah, pal);
        hmma_gemm<<<dim3(FF_ / 128, M / 128), 256, GSM_>>>(
            pah, pal,
            pwh + W_FC1_OFF + (size_t)l * FF_ * D_, pwl + W_FC1_OFF + (size_t)l * FF_ * D_,
            fc1_b + l * FF_, nullptr, pfh, pfl, FF_, D_, 2);
        hmma_gemm<<<dim3(D_ / 128, M / 128), 256, GSM_>>>(
            pfh, pfl,
            pwh + W_FC2_OFF + (size_t)l * D_ * FF_, pwl + W_FC2_OFF + (size_t)l * D_ * FF_,
            fc2_b + l * D_, px, nullptr, nullptr, D_, FF_, 1);
    }

    ln_hilo<<<M, 256>>>(px, lnf_g, lnf_b, pah, pal);
    hmma_gemm<<<dim3(V_ / 128, M / 128), 256, GSM_>>>(
        pah, pal, pwh + W_HEAD_OFF, pwl + W_HEAD_OFF,
        head_b, out, nullptr, nullptr, V_, D_, 0);
}

// round 17
// speedup vs baseline: 1.0991x; 1.0245x over previous
#include <cuda_runtime.h>
#include <cuda_bf16.h>
#include <math.h>
#include <stdint.h>

// Problem constants
#define L_   6
#define B_   2
#define T_   1024
#define D_   1024
#define H_   16
#define DH_  64
#define FF_  4096
#define V_   32000
#define KNB_ 4
#define DT_  0.1f

// ---------------------------------------------------------------------------
// Scratch
// ---------------------------------------------------------------------------
__device__ float g_x[B_ * T_ * D_];
__device__ float g_scores[(size_t)B_ * H_ * T_ * T_];
__device__ float g_part[2 * B_ * T_ * D_];           // split-K partials (16MB)

#define W_QKV_OFF  ((size_t)0)
#define W_QKV_N    ((size_t)L_ * 3 * D_ * D_)
#define W_OUT_OFF  (W_QKV_OFF + W_QKV_N)
#define W_OUT_N    ((size_t)L_ * D_ * D_)
#define W_FC1_OFF  (W_OUT_OFF + W_OUT_N)
#define W_FC1_N    ((size_t)L_ * FF_ * D_)
#define W_FC2_OFF  (W_FC1_OFF + W_FC1_N)
#define W_FC2_N    ((size_t)L_ * D_ * FF_)
#define W_HEAD_OFF (W_FC2_OFF + W_FC2_N)
#define W_HEAD_N   ((size_t)V_ * D_)
#define W_TOTAL    (W_HEAD_OFF + W_HEAD_N)

__device__ __nv_bfloat16 g_w_hi[W_TOTAL];
__device__ __nv_bfloat16 g_w_lo[W_TOTAL];
__device__ __nv_bfloat16 g_act_hi[B_ * T_ * D_];     // LN / attention outputs
__device__ __nv_bfloat16 g_act_lo[B_ * T_ * D_];
__device__ __nv_bfloat16 g_ff_hi[B_ * T_ * FF_];     // FC1 gelu output
__device__ __nv_bfloat16 g_ff_lo[B_ * T_ * FF_];
__device__ __nv_bfloat16 g_qkv_hi[B_ * T_ * 3 * D_]; // QKV proj, hi/lo
__device__ __nv_bfloat16 g_qkv_lo[B_ * T_ * 3 * D_];
__device__ __nv_bfloat16 g_p_hi[(size_t)B_ * H_ * T_ * T_];  // softmax probs
__device__ __nv_bfloat16 g_p_lo[(size_t)B_ * H_ * T_ * T_];
__device__ __nv_bfloat16 g_vt_hi[B_ * H_ * DH_ * T_];        // V transposed
__device__ __nv_bfloat16 g_vt_lo[B_ * H_ * DH_ * T_];

// ---------------------------------------------------------------------------
// helpers
// ---------------------------------------------------------------------------
__device__ __forceinline__ uint32_t smem_u32(const void* p) {
    uint32_t a;
    asm("{ .reg .u64 t; cvta.to.shared.u64 t, %1; cvt.u32.u64 %0, t; }" : "=r"(a) : "l"(p));
    return a;
}
__device__ __forceinline__ void ldmatrix_x4(uint32_t* r, uint32_t addr) {
    asm volatile("ldmatrix.sync.aligned.m8n8.x4.shared.b16 {%0,%1,%2,%3},[%4];"
                 : "=r"(r[0]), "=r"(r[1]), "=r"(r[2]), "=r"(r[3]) : "r"(addr));
}
__device__ __forceinline__ void mma_bf16(float* c, const uint32_t* a, const uint32_t* b) {
    asm volatile(
        "mma.sync.aligned.m16n8k16.row.col.f32.bf16.bf16.f32 "
        "{%0,%1,%2,%3},{%4,%5,%6,%7},{%8,%9},{%0,%1,%2,%3};"
        : "+f"(c[0]), "+f"(c[1]), "+f"(c[2]), "+f"(c[3])
        : "r"(a[0]), "r"(a[1]), "r"(a[2]), "r"(a[3]), "r"(b[0]), "r"(b[1]));
}
#define CP_ASYNC(dst, src) \
    asm volatile("cp.async.cg.shared.global [%0],[%1],16;" :: "r"(dst), "l"(src))
#define CP_COMMIT() asm volatile("cp.async.commit_group;")
#define CP_WAIT(N)  asm volatile("cp.async.wait_group %0;" :: "n"(N))

__device__ __forceinline__ void split2(float x, float y, uint32_t& h, uint32_t& l) {
    __nv_bfloat16 hx = __float2bfloat16(x);
    __nv_bfloat16 hy = __float2bfloat16(y);
    __nv_bfloat16 lx = __float2bfloat16(x - __bfloat162float(hx));
    __nv_bfloat16 ly = __float2bfloat16(y - __bfloat162float(hy));
    h = (uint32_t)__bfloat16_as_ushort(hx) | ((uint32_t)__bfloat16_as_ushort(hy) << 16);
    l = (uint32_t)__bfloat16_as_ushort(lx) | ((uint32_t)__bfloat16_as_ushort(ly) << 16);
}
__device__ __forceinline__ float gelu_f(float t) {
    float u = 0.7978845608028654f * (t + 0.044715f * t * t * t);
    return 0.5f * t * (1.0f + tanhf(u));
}

// ---------------------------------------------------------------------------
// fp32 -> bf16 hi/lo split (weights only)
// ---------------------------------------------------------------------------
__global__ void conv_hilo(const float* __restrict__ src,
                          __nv_bfloat16* __restrict__ hi,
                          __nv_bfloat16* __restrict__ lo, int n4) {
    int i = blockIdx.x * 256 + threadIdx.x;
    if (i >= n4) return;
    float4 v = ((const float4*)src)[i];
    uint2 ho, lu;
    split2(v.x, v.y, ho.x, lu.x);
    split2(v.z, v.w, ho.y, lu.y);
    *(uint2*)(hi + (size_t)4 * i) = ho;
    *(uint2*)(lo + (size_t)4 * i) = lu;
}

// ---------------------------------------------------------------------------
// HMMA NT-GEMM: 128x128 CTA tile, BK=32, 2-stage cp.async, regs capped at 128
// (2 CTAs/SM).  Ks = K-slice length (split-K via blockIdx.z; base K offset =
// blockIdx.z * Ks; Kd = full row stride).
// modes: 0 bias+store, 1 bias+add+store, 2 bias+gelu->hi/lo, 3 bias->hi/lo,
//        5 raw partial store to C + z*M*N (no bias; deterministic split-K).
// ---------------------------------------------------------------------------
#define RS_   80
#define AT_   (128 * RS_)          // 10240 bytes per operand tile
#define STG_  (4 * AT_)            // 40960 per stage
#define GSM_  (2 * STG_)           // 81920

__global__ __launch_bounds__(256, 2)
void hmma_gemm(const __nv_bfloat16* __restrict__ Ahi, const __nv_bfloat16* __restrict__ Alo,
               const __nv_bfloat16* __restrict__ Bhi, const __nv_bfloat16* __restrict__ Blo,
               const float* __restrict__ bias, float* __restrict__ C,
               __nv_bfloat16* __restrict__ Ohi, __nv_bfloat16* __restrict__ Olo,
               int N, int Kd, int Ks, int mode) {
    extern __shared__ char sm[];
    uint32_t smb = smem_u32(sm);
    int tid = threadIdx.x, wid = tid >> 5, lane = tid & 31;
    size_t m0 = (size_t)blockIdx.y * 128;
    size_t n0 = (size_t)blockIdx.x * 128;
    int kz = blockIdx.z;
    int wm = (wid & 1) * 64;
    int wn = (wid >> 1) * 32;

    const __nv_bfloat16* Ah = Ahi + m0 * (size_t)Kd + (size_t)kz * Ks;
    const __nv_bfloat16* Al = Alo + m0 * (size_t)Kd + (size_t)kz * Ks;
    const __nv_bfloat16* Bh = Bhi + n0 * (size_t)Kd + (size_t)kz * Ks;
    const __nv_bfloat16* Bl = Blo + n0 * (size_t)Kd + (size_t)kz * Ks;

    auto load_stage = [&](int i, int s) {
        int k0 = i << 5;
        uint32_t sb = smb + s * STG_;
        #pragma unroll
        for (int t = 0; t < 2; t++) {
            int idx = tid + t * 256;
            int row = idx >> 2, ch = idx & 3;
            size_t go = (size_t)row * Kd + k0 + ch * 8;
            uint32_t so = row * RS_ + ch * 16;
            CP_ASYNC(sb + so,            Ah + go);
            CP_ASYNC(sb + AT_ + so,      Al + go);
            CP_ASYNC(sb + 2 * AT_ + so,  Bh + go);
            CP_ASYNC(sb + 3 * AT_ + so,  Bl + go);
        }
        CP_COMMIT();
    };

    float acc[4][4][4];
    #pragma unroll
    for (int a = 0; a < 4; a++)
        #pragma unroll
        for (int b = 0; b < 4; b++)
            #pragma unroll
            for (int c = 0; c < 4; c++) acc[a][b][c] = 0.f;

    int NC = Ks >> 5;
    load_stage(0, 0);

    int r16  = lane & 15;
    int ah16 = (lane >> 4) * 16;
    int brow = ((lane >> 4) & 1) * 8 + (lane & 7);
    int bo16 = ((lane >> 3) & 1) * 16;

    for (int i = 0; i < NC; i++) {
        int s = i & 1;
        if (i + 1 < NC) { load_stage(i + 1, s ^ 1); CP_WAIT(1); }
        else            { CP_WAIT(0); }
        __syncthreads();

        uint32_t sa = smb + s * STG_;
        #pragma unroll
        for (int j = 0; j < 2; j++) {
            uint32_t a_hi[4][4], a_lo[4][4];
            #pragma unroll
            for (int mt = 0; mt < 4; mt++) {
                uint32_t addr = sa + (wm + mt * 16 + r16) * RS_ + ah16 + j * 32;
                ldmatrix_x4(a_hi[mt], addr);
                ldmatrix_x4(a_lo[mt], addr + AT_);
            }
            uint32_t b_hi[2][4], b_lo[2][4];
            #pragma unroll
            for (int p = 0; p < 2; p++) {
                uint32_t addr = sa + 2 * AT_ + (wn + p * 16 + brow) * RS_ + bo16 + j * 32;
                ldmatrix_x4(b_hi[p], addr);
                ldmatrix_x4(b_lo[p], addr + AT_);
            }
            #pragma unroll
            for (int mt = 0; mt < 4; mt++)
                #pragma unroll
                for (int nt = 0; nt < 4; nt++)
                    mma_bf16(acc[mt][nt], a_hi[mt], &b_hi[nt >> 1][(nt & 1) * 2]);
            #pragma unroll
            for (int mt = 0; mt < 4; mt++)
                #pragma unroll
                for (int nt = 0; nt < 4; nt++)
                    mma_bf16(acc[mt][nt], a_hi[mt], &b_lo[nt >> 1][(nt & 1) * 2]);
            #pragma unroll
            for (int mt = 0; mt < 4; mt++)
                #pragma unroll
                for (int nt = 0; nt < 4; nt++)
                    mma_bf16(acc[mt][nt], a_lo[mt], &b_hi[nt >> 1][(nt & 1) * 2]);
        }
        __syncthreads();
    }

    int gr = lane >> 2;
    int gc = (lane & 3) * 2;
    size_t zoff = (mode == 5) ? (size_t)kz * (size_t)gridDim.y * 128 * (size_t)N : 0;
    #pragma unroll
    for (int mt = 0; mt < 4; mt++) {
        size_t row = m0 + wm + mt * 16 + gr;
        #pragma unroll
        for (int nt = 0; nt < 4; nt++) {
            size_t col = n0 + wn + nt * 8 + gc;
            size_t o0 = row * (size_t)N + col;
            size_t o1 = (row + 8) * (size_t)N + col;
            if (mode == 5) {
                float2 w0 = {acc[mt][nt][0], acc[mt][nt][1]};
                float2 w1 = {acc[mt][nt][2], acc[mt][nt][3]};
                *(float2*)(C + zoff + o0) = w0;
                *(float2*)(C + zoff + o1) = w1;
                continue;
            }
            float2 bv = *(const float2*)(bias + col);
            float v00 = acc[mt][nt][0] + bv.x, v01 = acc[mt][nt][1] + bv.y;
            float v10 = acc[mt][nt][2] + bv.x, v11 = acc[mt][nt][3] + bv.y;
            if (mode >= 2) {
                if (mode == 2) {
                    v00 = gelu_f(v00); v01 = gelu_f(v01);
                    v10 = gelu_f(v10); v11 = gelu_f(v11);
                }
                uint32_t h0, l0, h1, l1;
                split2(v00, v01, h0, l0);
                split2(v10, v11, h1, l1);
                *(uint32_t*)(Ohi + o0) = h0; *(uint32_t*)(Olo + o0) = l0;
                *(uint32_t*)(Ohi + o1) = h1; *(uint32_t*)(Olo + o1) = l1;
            } else {
                if (mode == 1) {
                    float2 a0 = *(float2*)(C + o0), a1 = *(float2*)(C + o1);
                    v00 += a0.x; v01 += a0.y; v10 += a1.x; v11 += a1.y;
                }
                float2 w0 = {v00, v01}, w1 = {v10, v11};
                *(float2*)(C + o0) = w0;
                *(float2*)(C + o1) = w1;
            }
        }
    }
}

// ---------------------------------------------------------------------------
// split-K combine: x[row,:] += part0 + part1 + bias   (N = D fixed 1024)
// ---------------------------------------------------------------------------
__global__ void combine2(float* __restrict__ x, const float* __restrict__ part,
                         const float* __restrict__ bias) {
    size_t row = blockIdx.x;
    int c = threadIdx.x;                 // float4 index 0..255
    size_t idx = row * D_ + c * 4;
    float4 xv = *(float4*)(x + idx);
    float4 p0 = *(const float4*)(part + idx);
    float4 p1 = *(const float4*)(part + (size_t)B_ * T_ * D_ + idx);
    float4 bv = *(const float4*)(bias + c * 4);
    xv.x += p0.x + p1.x + bv.x;
    xv.y += p0.y + p1.y + bv.y;
    xv.z += p0.z + p1.z + bv.z;
    xv.w += p0.w + p1.w + bv.w;
    *(float4*)(x + idx) = xv;
}

// ---------------------------------------------------------------------------
// HMMA attention scores: per (b,h) 128x128 tile, K = DH = 64 in one stage.
// ---------------------------------------------------------------------------
#define SRS_  144
#define SAT_  (128 * SRS_)
#define SSM_  (4 * SAT_)

__global__ __launch_bounds__(256, 2)
void scores_hmma(const __nv_bfloat16* __restrict__ qh,
                 const __nv_bfloat16* __restrict__ ql, float scale) {
    extern __shared__ char sm[];
    uint32_t smb = smem_u32(sm);
    int tid = threadIdx.x, wid = tid >> 5, lane = tid & 31;
    int bh = blockIdx.z;
    int b = bh >> 4, h = bh & 15;
    size_t m0 = (size_t)blockIdx.y * 128;
    size_t n0 = (size_t)blockIdx.x * 128;
    int wm = (wid & 1) * 64;
    int wn = (wid >> 1) * 32;

    const __nv_bfloat16* Ah = qh + ((size_t)b * T_ + m0) * (3 * D_) + h * DH_;
    const __nv_bfloat16* Al = ql + ((size_t)b * T_ + m0) * (3 * D_) + h * DH_;
    const __nv_bfloat16* Bh = qh + ((size_t)b * T_ + n0) * (3 * D_) + D_ + h * DH_;
    const __nv_bfloat16* Bl = ql + ((size_t)b * T_ + n0) * (3 * D_) + D_ + h * DH_;

    const __nv_bfloat16* srcs[4] = {Ah, Al, Bh, Bl};
    #pragma unroll
    for (int tile = 0; tile < 4; tile++) {
        #pragma unroll
        for (int t = 0; t < 4; t++) {
            int idx = tid + t * 256;
            int r = idx >> 3, ch = idx & 7;
            CP_ASYNC(smb + tile * SAT_ + r * SRS_ + ch * 16,
                     srcs[tile] + (size_t)r * (3 * D_) + ch * 8);
        }
    }
    CP_COMMIT();
    CP_WAIT(0);
    __syncthreads();

    float acc[4][4][4];
    #pragma unroll
    for (int a = 0; a < 4; a++)
        #pragma unroll
        for (int bq = 0; bq < 4; bq++)
            #pragma unroll
            for (int c = 0; c < 4; c++) acc[a][bq][c] = 0.f;

    int r16  = lane & 15;
    int ah16 = (lane >> 4) * 16;
    int brow = ((lane >> 4) & 1) * 8 + (lane & 7);
    int bo16 = ((lane >> 3) & 1) * 16;

    #pragma unroll
    for (int j = 0; j < 4; j++) {
        uint32_t a_hi[4][4], a_lo[4][4];
        #pragma unroll
        for (int mt = 0; mt < 4; mt++) {
            uint32_t addr = smb + (wm + mt * 16 + r16) * SRS_ + ah16 + j * 32;
            ldmatrix_x4(a_hi[mt], addr);
            ldmatrix_x4(a_lo[mt], addr + SAT_);
        }
        uint32_t b_hi[2][4], b_lo[2][4];
        #pragma unroll
        for (int p = 0; p < 2; p++) {
            uint32_t addr = smb + 2 * SAT_ + (wn + p * 16 + brow) * SRS_ + bo16 + j * 32;
            ldmatrix_x4(b_hi[p], addr);
            ldmatrix_x4(b_lo[p], addr + SAT_);
        }
        #pragma unroll
        for (int mt = 0; mt < 4; mt++)
            #pragma unroll
            for (int nt = 0; nt < 4; nt++)
                mma_bf16(acc[mt][nt], a_hi[mt], &b_hi[nt >> 1][(nt & 1) * 2]);
        #pragma unroll
        for (int mt = 0; mt < 4; mt++)
            #pragma unroll
            for (int nt = 0; nt < 4; nt++)
                mma_bf16(acc[mt][nt], a_hi[mt], &b_lo[nt >> 1][(nt & 1) * 2]);
        #pragma unroll
        for (int mt = 0; mt < 4; mt++)
            #pragma unroll
            for (int nt = 0; nt < 4; nt++)
                mma_bf16(acc[mt][nt], a_lo[mt], &b_hi[nt >> 1][(nt & 1) * 2]);
    }

    float* srow = g_scores + (size_t)bh * T_ * T_;
    int gr = lane >> 2;
    int gc = (lane & 3) * 2;
    #pragma unroll
    for (int mt = 0; mt < 4; mt++) {
        size_t row = m0 + wm + mt * 16 + gr;
        #pragma unroll
        for (int nt = 0; nt < 4; nt++) {
            size_t col = n0 + wn + nt * 8 + gc;
            float2 w0 = {acc[mt][nt][0] * scale, acc[mt][nt][1] * scale};
            float2 w1 = {acc[mt][nt][2] * scale, acc[mt][nt][3] * scale};
            *(float2*)(srow + row * T_ + col) = w0;
            *(float2*)(srow + (row + 8) * T_ + col) = w1;
        }
    }
}

// ---------------------------------------------------------------------------
// V transpose: [b,k,h,dh] hi/lo -> [b,h,dh,k] hi/lo
// ---------------------------------------------------------------------------
__global__ void vt_kernel(const __nv_bfloat16* __restrict__ qh,
                          const __nv_bfloat16* __restrict__ ql,
                          __nv_bfloat16* __restrict__ vth,
                          __nv_bfloat16* __restrict__ vtl) {
    __shared__ __align__(16) __nv_bfloat16 th[64][72];
    __shared__ __align__(16) __nv_bfloat16 tl[64][72];
    int bh = blockIdx.y;
    int b = bh >> 4, h = bh & 15;
    int k0 = blockIdx.x * 64;
    int tid = threadIdx.x;
    const __nv_bfloat16* inh = qh + ((size_t)b * T_ + k0) * (3 * D_) + 2 * D_ + h * DH_;
    const __nv_bfloat16* inl = ql + ((size_t)b * T_ + k0) * (3 * D_) + 2 * D_ + h * DH_;
    #pragma unroll
    for (int t = 0; t < 2; t++) {
        int idx = tid + t * 256;
        int r = idx >> 3, c = idx & 7;
        *(uint4*)&th[r][c * 8] = *(const uint4*)(inh + (size_t)r * (3 * D_) + c * 8);
        *(uint4*)&tl[r][c * 8] = *(const uint4*)(inl + (size_t)r * (3 * D_) + c * 8);
    }
    __syncthreads();
    #pragma unroll
    for (int t = 0; t < 2; t++) {
        int idx = tid + t * 256;
        int dh = idx >> 3, c = idx & 7;
        __nv_bfloat16 bh8[8], bl8[8];
        #pragma unroll
        for (int u = 0; u < 8; u++) { bh8[u] = th[c * 8 + u][dh]; bl8[u] = tl[c * 8 + u][dh]; }
        size_t off = ((size_t)bh * DH_ + dh) * T_ + k0 + c * 8;
        *(uint4*)(vth + off) = *(uint4*)bh8;
        *(uint4*)(vtl + off) = *(uint4*)bl8;
    }
}

// ---------------------------------------------------------------------------
// Row softmax over T=1024: fp32 scores -> P bf16 hi/lo
// ---------------------------------------------------------------------------
__global__ void softmax_kernel(__nv_bfloat16* __restrict__ phi,
                               __nv_bfloat16* __restrict__ plo) {
    size_t row = blockIdx.x;
    int c = threadIdx.x;
    const float4* rp = (const float4*)(g_scores + row * T_);
    float4 v = rp[c];
    float m = fmaxf(fmaxf(v.x, v.y), fmaxf(v.z, v.w));
    #pragma unroll
    for (int o = 16; o; o >>= 1) m = fmaxf(m, __shfl_down_sync(0xFFFFFFFFu, m, o));
    __shared__ float sm[8];
    __shared__ float bm, bs;
    if ((c & 31) == 0) sm[c >> 5] = m;
    __syncthreads();
    if (c == 0) {
        float mm = sm[0];
        #pragma unroll
        for (int i = 1; i < 8; i++) mm = fmaxf(mm, sm[i]);
        bm = mm;
    }
    __syncthreads();
    float mm = bm;
    v.x = __expf(v.x - mm); v.y = __expf(v.y - mm);
    v.z = __expf(v.z - mm); v.w = __expf(v.w - mm);
    float s = v.x + v.y + v.z + v.w;
    #pragma unroll
    for (int o = 16; o; o >>= 1) s += __shfl_down_sync(0xFFFFFFFFu, s, o);
    if ((c & 31) == 0) sm[c >> 5] = s;
    __syncthreads();
    if (c == 0) {
        float S = 0.f;
        #pragma unroll
        for (int i = 0; i < 8; i++) S += sm[i];
        bs = 1.0f / S;
    }
    __syncthreads();
    float inv = bs;
    uint2 ho, lu;
    split2(v.x * inv, v.y * inv, ho.x, lu.x);
    split2(v.z * inv, v.w * inv, ho.y, lu.y);
    *(uint2*)(phi + row * T_ + c * 4) = ho;
    *(uint2*)(plo + row * T_ + c * 4) = lu;
}

// ---------------------------------------------------------------------------
// HMMA AV: per (b,h) O[1024,64] = P[1024,1024] * Vt[64,1024]^T
// ---------------------------------------------------------------------------
#define VAT_  (128 * RS_)
#define VBT_  (64 * RS_)
#define VSTG_ (2 * VAT_ + 2 * VBT_)
#define VSM_  (2 * VSTG_)

__global__ __launch_bounds__(256, 2)
void av_hmma(const __nv_bfloat16* __restrict__ Phi, const __nv_bfloat16* __restrict__ Plo,
             const __nv_bfloat16* __restrict__ Vth, const __nv_bfloat16* __restrict__ Vtl,
             __nv_bfloat16* __restrict__ Ohi, __nv_bfloat16* __restrict__ Olo) {
    extern __shared__ char sm[];
    uint32_t smb = smem_u32(sm);
    int tid = threadIdx.x, wid = tid >> 5, lane = tid & 31;
    int bh = blockIdx.y;
    int b = bh >> 4, h = bh & 15;
    size_t m0 = (size_t)blockIdx.x * 128;
    int wm = (wid & 1) * 64;
    int wn = (wid >> 1) * 16;

    const __nv_bfloat16* Ah = Phi + (size_t)bh * T_ * T_ + m0 * T_;
    const __nv_bfloat16* Al = Plo + (size_t)bh * T_ * T_ + m0 * T_;
    const __nv_bfloat16* Bh = Vth + (size_t)bh * DH_ * T_;
    const __nv_bfloat16* Bl = Vtl + (size_t)bh * DH_ * T_;

    auto load_stage = [&](int i, int s) {
        int k0 = i << 5;
        uint32_t sb = smb + s * VSTG_;
        #pragma unroll
        for (int t = 0; t < 2; t++) {
            int idx = tid + t * 256;
            int row = idx >> 2, ch = idx & 3;
            size_t go = (size_t)row * T_ + k0 + ch * 8;
            uint32_t so = row * RS_ + ch * 16;
            CP_ASYNC(sb + so,        Ah + go);
            CP_ASYNC(sb + VAT_ + so, Al + go);
        }
        {
            int row = tid >> 2, ch = tid & 3;
            size_t go = (size_t)row * T_ + k0 + ch * 8;
            uint32_t so = row * RS_ + ch * 16;
            CP_ASYNC(sb + 2 * VAT_ + so,        Bh + go);
            CP_ASYNC(sb + 2 * VAT_ + VBT_ + so, Bl + go);
        }
        CP_COMMIT();
    };

    float acc[4][2][4];
    #pragma unroll
    for (int a = 0; a < 4; a++)
        #pragma unroll
        for (int bq = 0; bq < 2; bq++)
            #pragma unroll
            for (int c = 0; c < 4; c++) acc[a][bq][c] = 0.f;

    int NC = T_ >> 5;
    load_stage(0, 0);

    int r16  = lane & 15;
    int ah16 = (lane >> 4) * 16;
    int brow = ((lane >> 4) & 1) * 8 + (lane & 7);
    int bo16 = ((lane >> 3) & 1) * 16;

    for (int i = 0; i < NC; i++) {
        int s = i & 1;
        if (i + 1 < NC) { load_stage(i + 1, s ^ 1); CP_WAIT(1); }
        else            { CP_WAIT(0); }
        __syncthreads();

        uint32_t sa = smb + s * VSTG_;
        #pragma unroll
        for (int j = 0; j < 2; j++) {
            uint32_t a_hi[4][4], a_lo[4][4];
            #pragma unroll
            for (int mt = 0; mt < 4; mt++) {
                uint32_t addr = sa + (wm + mt * 16 + r16) * RS_ + ah16 + j * 32;
                ldmatrix_x4(a_hi[mt], addr);
                ldmatrix_x4(a_lo[mt], addr + VAT_);
            }
            uint32_t b_hi[4], b_lo[4];
            {
                uint32_t addr = sa + 2 * VAT_ + (wn + brow) * RS_ + bo16 + j * 32;
                ldmatrix_x4(b_hi, addr);
                ldmatrix_x4(b_lo, addr + VBT_);
            }
            #pragma unroll
            for (int mt = 0; mt < 4; mt++)
                #pragma unroll
                for (int nt = 0; nt < 2; nt++)
                    mma_bf16(acc[mt][nt], a_hi[mt], &b_hi[nt * 2]);
            #pragma unroll
            for (int mt = 0; mt < 4; mt++)
                #pragma unroll
                for (int nt = 0; nt < 2; nt++)
                    mma_bf16(acc[mt][nt], a_hi[mt], &b_lo[nt * 2]);
            #pragma unroll
            for (int mt = 0; mt < 4; mt++)
                #pragma unroll
                for (int nt = 0; nt < 2; nt++)
                    mma_bf16(acc[mt][nt], a_lo[mt], &b_hi[nt * 2]);
        }
        __syncthreads();
    }

    int gr = lane >> 2;
    int gc = (lane & 3) * 2;
    #pragma unroll
    for (int mt = 0; mt < 4; mt++) {
        size_t row = m0 + wm + mt * 16 + gr;
        #pragma unroll
        for (int nt = 0; nt < 2; nt++) {
            int col = wn + nt * 8 + gc;
            size_t o0 = ((size_t)b * T_ + row) * D_ + h * DH_ + col;
            size_t o1 = ((size_t)b * T_ + row + 8) * D_ + h * DH_ + col;
            uint32_t h0, l0, h1, l1;
            split2(acc[mt][nt][0], acc[mt][nt][1], h0, l0);
            split2(acc[mt][nt][2], acc[mt][nt][3], h1, l1);
            *(uint32_t*)(Ohi + o0) = h0; *(uint32_t*)(Olo + o0) = l0;
            *(uint32_t*)(Ohi + o1) = h1; *(uint32_t*)(Olo + o1) = l1;
        }
    }
}

// ---------------------------------------------------------------------------
// Embedding
// ---------------------------------------------------------------------------
__global__ void embed_kernel(const int* __restrict__ tokens,
                             const float* __restrict__ embed,
                             const float* __restrict__ pos) {
    int row = blockIdx.x;
    int t = row & (T_ - 1);
    int tok = tokens[row];
    const float4* e = (const float4*)(embed + (size_t)tok * D_);
    const float4* p = (const float4*)(pos + (size_t)t * D_);
    float4* o = (float4*)(g_x + (size_t)row * D_);
    int c = threadIdx.x;
    float4 ev = e[c], pv = p[c];
    ev.x += pv.x; ev.y += pv.y; ev.z += pv.z; ev.w += pv.w;
    o[c] = ev;
}

// ---------------------------------------------------------------------------
// Kuramoto (bias cancels in softmax)
// ---------------------------------------------------------------------------
__global__ void kuramoto_kernel(const float* __restrict__ phase,
                                const float* __restrict__ freq,
                                const float* __restrict__ coupling,
                                const float* __restrict__ nbr_w,
                                const int* __restrict__ nbr_idx,
                                float* __restrict__ out_tail) {
    int i = threadIdx.x;
    if (i < L_ * H_) {
        int l = i / H_;
        float ph = phase[i];
        float sync = 0.0f;
        #pragma unroll
        for (int k = 0; k < KNB_; k++) {
            int id = nbr_idx[i * KNB_ + k];
            sync += nbr_w[i * KNB_ + k] * sinf(phase[l * H_ + id] - ph);
        }
        out_tail[i] = ph + DT_ * (freq[i] + coupling[l] * sync);
    }
}

// ---------------------------------------------------------------------------
// LayerNorm -> bf16 hi/lo
// ---------------------------------------------------------------------------
__global__ void ln_hilo(const float* __restrict__ x,
                        const float* __restrict__ g,
                        const float* __restrict__ b,
                        __nv_bfloat16* __restrict__ hi,
                        __nv_bfloat16* __restrict__ lo) {
    int row = blockIdx.x;
    int c = threadIdx.x;
    float4 v = ((const float4*)(x + (size_t)row * D_))[c];
    float s  = v.x + v.y + v.z + v.w;
    float s2 = v.x * v.x + v.y * v.y + v.z * v.z + v.w * v.w;
    #pragma unroll
    for (int o = 16; o; o >>= 1) {
        s  += __shfl_down_sync(0xFFFFFFFFu, s, o);
        s2 += __shfl_down_sync(0xFFFFFFFFu, s2, o);
    }
    __shared__ float ss[8], ss2[8];
    __shared__ float mu_s, rstd_s;
    if ((c & 31) == 0) { ss[c >> 5] = s; ss2[c >> 5] = s2; }
    __syncthreads();
    if (c == 0) {
        float S = 0.f, S2 = 0.f;
        #pragma unroll
        for (int i = 0; i < 8; i++) { S += ss[i]; S2 += ss2[i]; }
        float mu = S * (1.0f / D_);
        float var = S2 * (1.0f / D_) - mu * mu;
        mu_s = mu;
        rstd_s = rsqrtf(var + 1e-5f);
    }
    __syncthreads();
    float mu = mu_s, rstd = rstd_s;
    float4 gv = ((const float4*)g)[c];
    float4 bv = ((const float4*)b)[c];
    float o0 = (v.x - mu) * rstd * gv.x + bv.x;
    float o1 = (v.y - mu) * rstd * gv.y + bv.y;
    float o2 = (v.z - mu) * rstd * gv.z + bv.z;
    float o3 = (v.w - mu) * rstd * gv.w + bv.w;
    uint2 ho, lu;
    split2(o0, o1, ho.x, lu.x);
    split2(o2, o3, ho.y, lu.y);
    *(uint2*)(hi + (size_t)row * D_ + c * 4) = ho;
    *(uint2*)(lo + (size_t)row * D_ + c * 4) = lu;
}

// ---------------------------------------------------------------------------
// Host launcher
// ---------------------------------------------------------------------------
static inline void launch_conv(const float* src, __nv_bfloat16* hi, __nv_bfloat16* lo, size_t n) {
    int n4 = (int)(n / 4);
    conv_hilo<<<(n4 + 255) / 256, 256>>>(src, hi, lo, n4);
}

extern "C" void kernel_launch(void* const* d_in, const int* in_sizes, int n_in,
                              void* d_out, int out_size) {
    const int*   tokens   = (const int*)  d_in[0];
    const float* embed    = (const float*)d_in[1];
    const float* pos      = (const float*)d_in[2];
    const float* qkv_w    = (const float*)d_in[3];
    const float* qkv_b    = (const float*)d_in[4];
    const float* out_w    = (const float*)d_in[5];
    const float* out_b    = (const float*)d_in[6];
    const float* fc1_w    = (const float*)d_in[7];
    const float* fc1_b    = (const float*)d_in[8];
    const float* fc2_w    = (const float*)d_in[9];
    const float* fc2_b    = (const float*)d_in[10];
    const float* ln1_g    = (const float*)d_in[11];
    const float* ln1_b    = (const float*)d_in[12];
    const float* ln2_g    = (const float*)d_in[13];
    const float* ln2_b    = (const float*)d_in[14];
    const float* lnf_g    = (const float*)d_in[15];
    const float* lnf_b    = (const float*)d_in[16];
    const float* head_w   = (const float*)d_in[17];
    const float* head_b   = (const float*)d_in[18];
    const float* phase    = (const float*)d_in[19];
    const float* freq     = (const float*)d_in[20];
    const float* coupling = (const float*)d_in[21];
    const float* nbr_w    = (const float*)d_in[22];
    const int*   nbr_idx  = (const int*)  d_in[23];
    float* out = (float*)d_out;

    float *px, *ppart;
    __nv_bfloat16 *pwh, *pwl, *pah, *pal, *pfh, *pfl, *pqh, *pql, *pph, *ppl, *pvh, *pvl;
    cudaGetSymbolAddress((void**)&px, g_x);
    cudaGetSymbolAddress((void**)&ppart, g_part);
    cudaGetSymbolAddress((void**)&pwh, g_w_hi);
    cudaGetSymbolAddress((void**)&pwl, g_w_lo);
    cudaGetSymbolAddress((void**)&pah, g_act_hi);
    cudaGetSymbolAddress((void**)&pal, g_act_lo);
    cudaGetSymbolAddress((void**)&pfh, g_ff_hi);
    cudaGetSymbolAddress((void**)&pfl, g_ff_lo);
    cudaGetSymbolAddress((void**)&pqh, g_qkv_hi);
    cudaGetSymbolAddress((void**)&pql, g_qkv_lo);
    cudaGetSymbolAddress((void**)&pph, g_p_hi);
    cudaGetSymbolAddress((void**)&ppl, g_p_lo);
    cudaGetSymbolAddress((void**)&pvh, g_vt_hi);
    cudaGetSymbolAddress((void**)&pvl, g_vt_lo);

    cudaFuncSetAttribute(hmma_gemm,   cudaFuncAttributeMaxDynamicSharedMemorySize, GSM_);
    cudaFuncSetAttribute(scores_hmma, cudaFuncAttributeMaxDynamicSharedMemorySize, SSM_);
    cudaFuncSetAttribute(av_hmma,     cudaFuncAttributeMaxDynamicSharedMemorySize, VSM_);

    const int M = B_ * T_;
    const float scale = 1.0f / 8.0f;

    // launch index 3 (ncu's consistent -s5 capture slot) = layer-0 QKV gemm
    embed_kernel<<<M, 256>>>(tokens, embed, pos);                          // 0
    launch_conv(qkv_w, pwh + W_QKV_OFF, pwl + W_QKV_OFF, W_QKV_N);         // 1
    ln_hilo<<<M, 256>>>(px, ln1_g, ln1_b, pah, pal);                       // 2
    hmma_gemm<<<dim3(3 * D_ / 128, M / 128), 256, GSM_>>>(                 // 3 (profiled)
        pah, pal, pwh + W_QKV_OFF, pwl + W_QKV_OFF,
        qkv_b, nullptr, pqh, pql, 3 * D_, D_, D_, 3);
    kuramoto_kernel<<<1, 128>>>(phase, freq, coupling, nbr_w, nbr_idx,
                                out + (size_t)B_ * T_ * V_);
    launch_conv(out_w,  pwh + W_OUT_OFF,  pwl + W_OUT_OFF,  W_OUT_N);
    launch_conv(fc1_w,  pwh + W_FC1_OFF,  pwl + W_FC1_OFF,  W_FC1_N);
    launch_conv(fc2_w,  pwh + W_FC2_OFF,  pwl + W_FC2_OFF,  W_FC2_N);
    launch_conv(head_w, pwh + W_HEAD_OFF, pwl + W_HEAD_OFF, W_HEAD_N);

    for (int l = 0; l < L_; l++) {
        if (l > 0) {
            ln_hilo<<<M, 256>>>(px, ln1_g + l * D_, ln1_b + l * D_, pah, pal);
            hmma_gemm<<<dim3(3 * D_ / 128, M / 128), 256, GSM_>>>(
                pah, pal,
                pwh + W_QKV_OFF + (size_t)l * 3 * D_ * D_, pwl + W_QKV_OFF + (size_t)l * 3 * D_ * D_,
                qkv_b + l * 3 * D_, nullptr, pqh, pql, 3 * D_, D_, D_, 3);
        }
        vt_kernel<<<dim3(T_ / 64, B_ * H_), 256>>>(pqh, pql, pvh, pvl);
        scores_hmma<<<dim3(T_ / 128, T_ / 128, B_ * H_), 256, SSM_>>>(pqh, pql, scale);
        softmax_kernel<<<B_ * H_ * T_, 256>>>(pph, ppl);
        av_hmma<<<dim3(T_ / 128, B_ * H_), 256, VSM_>>>(pph, ppl, pvh, pvl, pah, pal);
        // out-proj: split-K=2 (grid 8x16x2 = 256 CTAs), deterministic combine
        hmma_gemm<<<dim3(D_ / 128, M / 128, 2), 256, GSM_>>>(
            pah, pal,
            pwh + W_OUT_OFF + (size_t)l * D_ * D_, pwl + W_OUT_OFF + (size_t)l * D_ * D_,
            nullptr, ppart, nullptr, nullptr, D_, D_, D_ / 2, 5);
        combine2<<<M, 256>>>(px, ppart, out_b + l * D_);
        ln_hilo<<<M, 256>>>(px, ln2_g + l * D_, ln2_b + l * D_, pah, pal);
        hmma_gemm<<<dim3(FF_ / 128, M / 128), 256, GSM_>>>(
            pah, pal,
            pwh + W_FC1_OFF + (size_t)l * FF_ * D_, pwl + W_FC1_OFF + (size_t)l * FF_ * D_,
            fc1_b + l * FF_, nullptr, pfh, pfl, FF_, D_, D_, 2);
        // FC2: split-K=2 (K=4096 -> 2048 per slice)
        hmma_gemm<<<dim3(D_ / 128, M / 128, 2), 256, GSM_>>>(
            pfh, pfl,
            pwh + W_FC2_OFF + (size_t)l * D_ * FF_, pwl + W_FC2_OFF + (size_t)l * D_ * FF_,
            nullptr, ppart, nullptr, nullptr, D_, FF_, FF_ / 2, 5);
        combine2<<<M, 256>>>(px, ppart, fc2_b + l * D_);
    }

    ln_hilo<<<M, 256>>>(px, lnf_g, lnf_b, pah, pal);
    hmma_gemm<<<dim3(V_ / 128, M / 128), 256, GSM_>>>(
        pah, pal, pwh + W_HEAD_OFF, pwl + W_HEAD_OFF,
        head_b, out, nullptr, nullptr, V_, D_, D_, 0);
}